// round 2
// baseline (speedup 1.0000x reference)
#include <cuda_runtime.h>
#include <math.h>

#define Bt   32
#define S    256
#define T    8192      // Bt*S
#define D    512
#define PD   588
#define NH   8
#define HD   64
#define E    8
#define HID  2048
#define NSLOT 16896    // 16384 + 8*64 padding

// ---------------- scratch (static device allocations, allowed) --------------
__device__ float g_patches[(long)T*PD];
__device__ float g_e[(long)T*D];
__device__ float g_ln[(long)T*D];
__device__ float g_q[(long)T*D];
__device__ float g_k[(long)T*D];
__device__ float g_v[(long)T*D];
__device__ float g_kT[(long)Bt*NH*HD*S];
__device__ float g_attn[(long)Bt*NH*S*S];
__device__ float g_av[(long)T*D];
__device__ float g_x2[(long)T*D];
__device__ float g_probs[(long)T*E];
__device__ int   g_topi[T*2];
__device__ float g_topv[T*2];
__device__ int   g_btok[NSLOT];
__device__ float g_bgate[NSLOT];
__device__ int   g_slot[T*2];
__device__ int   g_eoff[E];
__device__ int   g_ecnt[E];
__device__ int   g_ecnt_raw[E];
__device__ float g_hbuf[(long)NSLOT*HID];
__device__ float g_contrib[(long)NSLOT*D];
__device__ float g_o1[(long)T*D];
__device__ float g_o2[(long)T*D];
__device__ float g_loss[1];

// ---------------- patchify -------------------------------------------------
__global__ void patchify_k(const float* __restrict__ x, float* __restrict__ out)
{
    long idx = (long)blockIdx.x*blockDim.x + threadIdx.x;
    long total = (long)T*PD;
    if (idx >= total) return;
    int i = idx % PD;
    long r = idx / PD;
    int s = r % S;
    int b = r / S;
    int c  = i % 3;
    int t  = i / 3;
    int p2 = t % 14;
    int p1 = t / 14;
    int hh = s >> 4, ww = s & 15;
    out[idx] = x[(((long)(b*3 + c)*224) + hh*14 + p1)*224 + ww*14 + p2];
}

// ---------------- generic tiled SGEMM with epilogues -----------------------
// epi: 0 plain(alpha) 1 +bias 2 +bias+pos 3 +bias+residual 4 gelu(+bias) 5 gate*( +bias)
#define BM 64
#define BN 64
#define BKk 16
__global__ void gemm_k(const float* __restrict__ A, const float* __restrict__ B,
                       float* __restrict__ C, int M, int N, int K,
                       int lda, int ldb, int ldc,
                       long sAo, long sAi, long sBo, long sBi, long sCo, long sCi, int zdiv,
                       float alpha,
                       const float* __restrict__ bias, long sBias,
                       const float* __restrict__ extra,
                       const int* __restrict__ gatherIdx,
                       const float* __restrict__ gates,
                       const int* __restrict__ eoff, const int* __restrict__ ecnt,
                       int epi)
{
    __shared__ float As[BKk][BM];
    __shared__ float Bs[BKk][BN+4];
    int z = blockIdx.z;
    int zo = z / zdiv, zi = z - zo*zdiv;
    const float* Ab = A + zo*sAo + zi*sAi;
    const float* Bb = B + zo*sBo + zi*sBi;
    float* Cb = C + zo*sCo + zi*sCi;
    int base = 0, Mloc = M;
    if (eoff) { base = eoff[z]; int c = ecnt[z]; Mloc = (c + BM - 1) & ~(BM - 1); }
    int tm = blockIdx.x*BM;
    if (tm >= Mloc) return;
    int tn = blockIdx.y*BN;
    const float* biasb = bias ? (bias + (long)z*sBias) : nullptr;

    int tid = threadIdx.x;
    int tx = tid & 15, ty = tid >> 4;
    float acc[4][4] = {};
    for (int k0 = 0; k0 < K; k0 += BKk) {
        #pragma unroll
        for (int t = 0; t < 4; t++) {
            int id = tid + t*256;
            int r = id >> 4, c = id & 15;
            int gr = tm + r;
            float v = 0.f;
            if (gr < Mloc && (k0 + c) < K) {
                int ar = gatherIdx ? gatherIdx[base + gr] : (base + gr);
                v = Ab[(long)ar*lda + k0 + c];
            }
            As[c][r] = v;
        }
        #pragma unroll
        for (int t = 0; t < 4; t++) {
            int id = tid + t*256;
            int r = id >> 6, c = id & 63;
            float v = 0.f;
            if ((k0 + r) < K && (tn + c) < N)
                v = Bb[(long)(k0 + r)*ldb + tn + c];
            Bs[r][c] = v;
        }
        __syncthreads();
        #pragma unroll
        for (int kk = 0; kk < BKk; kk++) {
            float av[4], bv[4];
            #pragma unroll
            for (int i = 0; i < 4; i++) av[i] = As[kk][ty*4 + i];
            #pragma unroll
            for (int j = 0; j < 4; j++) bv[j] = Bs[kk][tx*4 + j];
            #pragma unroll
            for (int i = 0; i < 4; i++)
                #pragma unroll
                for (int j = 0; j < 4; j++)
                    acc[i][j] = fmaf(av[i], bv[j], acc[i][j]);
        }
        __syncthreads();
    }
    #pragma unroll
    for (int i = 0; i < 4; i++) {
        int row = tm + ty*4 + i;
        if (row >= Mloc) continue;
        #pragma unroll
        for (int j = 0; j < 4; j++) {
            int col = tn + tx*4 + j;
            if (col >= N) continue;
            float v = acc[i][j]*alpha;
            if (epi >= 1) v += biasb[col];
            if (epi == 2) v += extra[(long)(row & (S-1))*ldc + col];
            else if (epi == 3) v += extra[(long)row*ldc + col];
            else if (epi == 4) v = 0.5f*v*(1.0f + erff(v*0.70710678118654752f));
            else if (epi == 5) v *= gates[base + row];
            Cb[(long)(base + row)*ldc + col] = v;
        }
    }
}

// ---------------- layernorm (warp per row of 512) --------------------------
__global__ void ln_k(const float* __restrict__ x, const float* __restrict__ g,
                     const float* __restrict__ b, float* __restrict__ y)
{
    int row  = (blockIdx.x*blockDim.x + threadIdx.x) >> 5;
    int lane = threadIdx.x & 31;
    if (row >= T) return;
    const float* xr = x + (long)row*D;
    float v[16]; float s = 0.f;
    #pragma unroll
    for (int i = 0; i < 16; i++) { v[i] = xr[lane + 32*i]; s += v[i]; }
    #pragma unroll
    for (int o = 16; o > 0; o >>= 1) s += __shfl_xor_sync(~0u, s, o);
    float mean = s*(1.f/D);
    float vs = 0.f;
    #pragma unroll
    for (int i = 0; i < 16; i++) { float d = v[i]-mean; vs += d*d; }
    #pragma unroll
    for (int o = 16; o > 0; o >>= 1) vs += __shfl_xor_sync(~0u, vs, o);
    float rstd = rsqrtf(vs*(1.f/D) + 1e-5f);
    float* yr = y + (long)row*D;
    #pragma unroll
    for (int i = 0; i < 16; i++) { int c = lane + 32*i; yr[c] = (v[i]-mean)*rstd*g[c] + b[c]; }
}

// ---------------- k transpose: [t, h*64+d] -> [(b*8+h)*64+d][j] ------------
__global__ void ktrans_k(const float* __restrict__ k, float* __restrict__ kT)
{
    long idx = (long)blockIdx.x*blockDim.x + threadIdx.x;
    long total = (long)Bt*NH*HD*S;
    if (idx >= total) return;
    int j = idx & 255; long r = idx >> 8;
    int d = r & 63; r >>= 6;
    int h = r & 7; int b = (int)(r >> 3);
    kT[idx] = k[((long)(b*S + j))*D + h*HD + d];
}

// ---------------- softmax over last dim (256), warp per row ----------------
__global__ void softmax_k(float* __restrict__ a, int rows)
{
    int row  = (blockIdx.x*blockDim.x + threadIdx.x) >> 5;
    int lane = threadIdx.x & 31;
    if (row >= rows) return;
    float* r = a + (long)row*S;
    float v[8]; float m = -1e30f;
    #pragma unroll
    for (int i = 0; i < 8; i++) { v[i] = r[lane + 32*i]; m = fmaxf(m, v[i]); }
    #pragma unroll
    for (int o = 16; o > 0; o >>= 1) m = fmaxf(m, __shfl_xor_sync(~0u, m, o));
    float s = 0.f;
    #pragma unroll
    for (int i = 0; i < 8; i++) { v[i] = expf(v[i]-m); s += v[i]; }
    #pragma unroll
    for (int o = 16; o > 0; o >>= 1) s += __shfl_xor_sync(~0u, s, o);
    float inv = 1.f/s;
    #pragma unroll
    for (int i = 0; i < 8; i++) r[lane + 32*i] = v[i]*inv;
}

// ---------------- head-mean + re-softmax -> attn_w -------------------------
__global__ void attnw_k(const float* __restrict__ attn, float* __restrict__ out)
{
    int row  = (blockIdx.x*blockDim.x + threadIdx.x) >> 5;  // b*256+i
    int lane = threadIdx.x & 31;
    if (row >= T) return;
    int b = row >> 8, i = row & 255;
    const float* base = attn + ((long)b*NH*S + i)*S;
    float v[8];
    #pragma unroll
    for (int t = 0; t < 8; t++) {
        int j = lane + 32*t; float s = 0.f;
        #pragma unroll
        for (int h = 0; h < NH; h++) s += base[(long)h*S*S + j];
        v[t] = s*0.125f;
    }
    float m = -1e30f;
    #pragma unroll
    for (int t = 0; t < 8; t++) m = fmaxf(m, v[t]);
    #pragma unroll
    for (int o = 16; o > 0; o >>= 1) m = fmaxf(m, __shfl_xor_sync(~0u, m, o));
    float s = 0.f;
    #pragma unroll
    for (int t = 0; t < 8; t++) { v[t] = expf(v[t]-m); s += v[t]; }
    #pragma unroll
    for (int o = 16; o > 0; o >>= 1) s += __shfl_xor_sync(~0u, s, o);
    float inv = 1.f/s;
    float* orow = out + (long)row*S;
    #pragma unroll
    for (int t = 0; t < 8; t++) orow[lane + 32*t] = v[t]*inv;
}

// ---------------- MoE routing: warp per token ------------------------------
__global__ void route_k(const float* __restrict__ xln, const float* __restrict__ rw,
                        const float* __restrict__ rb, float* __restrict__ probs,
                        int* __restrict__ topi, float* __restrict__ topv)
{
    int tok  = (blockIdx.x*blockDim.x + threadIdx.x) >> 5;
    int lane = threadIdx.x & 31;
    if (tok >= T) return;
    const float* xr = xln + (long)tok*D;
    float acc[E] = {};
    for (int d = lane; d < D; d += 32) {
        float xv = xr[d];
        #pragma unroll
        for (int e = 0; e < E; e++) acc[e] = fmaf(xv, rw[d*E + e], acc[e]);
    }
    #pragma unroll
    for (int e = 0; e < E; e++)
        #pragma unroll
        for (int o = 16; o > 0; o >>= 1) acc[e] += __shfl_xor_sync(~0u, acc[e], o);
    if (lane == 0) {
        float mx = -1e30f;
        #pragma unroll
        for (int e = 0; e < E; e++) { acc[e] += rb[e]; mx = fmaxf(mx, acc[e]); }
        float s = 0.f, p[E];
        #pragma unroll
        for (int e = 0; e < E; e++) { p[e] = expf(acc[e]-mx); s += p[e]; }
        float inv = 1.f/s;
        int i0 = 0; float v0 = -1.f;
        #pragma unroll
        for (int e = 0; e < E; e++) { p[e] *= inv; probs[(long)tok*E + e] = p[e];
                                      if (p[e] > v0) { v0 = p[e]; i0 = e; } }
        int i1 = 0; float v1 = -1.f;
        #pragma unroll
        for (int e = 0; e < E; e++) { if (e != i0 && p[e] > v1) { v1 = p[e]; i1 = e; } }
        topi[tok*2] = i0;  topv[tok*2] = v0;
        topi[tok*2+1] = i1; topv[tok*2+1] = v1;
    }
}

// ---------------- bucket build (single block) ------------------------------
__global__ void bucket_k(const int* __restrict__ topi, const float* __restrict__ topv,
                         int* __restrict__ btok, float* __restrict__ bgate,
                         int* __restrict__ slot, int* __restrict__ eoff,
                         int* __restrict__ ecnt, int* __restrict__ ecnt_raw)
{
    __shared__ int cnt[E], off[E], cur[E];
    int tid = threadIdx.x;
    if (tid < E) cnt[tid] = 0;
    __syncthreads();
    for (int t = tid; t < T; t += 256) {
        atomicAdd(&cnt[topi[t*2]], 1);
        atomicAdd(&cnt[topi[t*2+1]], 1);
    }
    __syncthreads();
    if (tid == 0) {
        int o = 0;
        for (int e = 0; e < E; e++) { off[e] = o; o += (cnt[e] + BM - 1) & ~(BM - 1); }
    }
    __syncthreads();
    if (tid < E) {
        cur[tid] = off[tid];
        eoff[tid] = off[tid];
        ecnt[tid] = cnt[tid];
        ecnt_raw[tid] = cnt[tid];
    }
    __syncthreads();
    for (int t = tid; t < T; t += 256) {
        #pragma unroll
        for (int k = 0; k < 2; k++) {
            int e = topi[t*2 + k];
            int pos = atomicAdd(&cur[e], 1);
            btok[pos] = t;
            bgate[pos] = topv[t*2 + k];
            slot[t*2 + k] = pos;
        }
    }
    __syncthreads();
    for (int e = 0; e < E; e++) {
        int start = off[e] + cnt[e];
        int end   = off[e] + ((cnt[e] + BM - 1) & ~(BM - 1));
        for (int p = start + tid; p < end; p += 256) { btok[p] = 0; bgate[p] = 0.f; }
    }
}

// ---------------- combine 2 slot contributions -----------------------------
__global__ void combine_k(const int* __restrict__ slot, const float* __restrict__ contrib,
                          float* __restrict__ out)
{
    long idx = (long)blockIdx.x*blockDim.x + threadIdx.x;
    if (idx >= (long)T*D) return;
    int t = (int)(idx >> 9), d = (int)(idx & 511);
    int s0 = slot[t*2], s1 = slot[t*2+1];
    out[idx] = contrib[(long)s0*D + d] + contrib[(long)s1*D + d];
}

// ---------------- aux loss (deterministic single block) --------------------
__global__ void loss_k(const float* __restrict__ probs, const int* __restrict__ ecnt_raw,
                       float* __restrict__ out, int accum)
{
    __shared__ float red[256*E];
    int tid = threadIdx.x;
    float acc[E] = {};
    for (int t = tid; t < T; t += 256)
        #pragma unroll
        for (int e = 0; e < E; e++) acc[e] += probs[(long)t*E + e];
    #pragma unroll
    for (int e = 0; e < E; e++) red[tid*E + e] = acc[e];
    __syncthreads();
    for (int s = 128; s > 0; s >>= 1) {
        if (tid < s)
            #pragma unroll
            for (int e = 0; e < E; e++) red[tid*E + e] += red[(tid + s)*E + e];
        __syncthreads();
    }
    if (tid == 0) {
        float l = 0.f;
        for (int e = 0; e < E; e++) {
            float imp  = red[e]*(1.f/T);
            float frac = (float)ecnt_raw[e]*(1.f/T);
            l += frac*imp;
        }
        l *= (float)E;
        if (accum) out[0] += l; else out[0] = l;
    }
}

// ---------------- fv mean over S -------------------------------------------
__global__ void fv_k(const float* __restrict__ o2, float* __restrict__ fv)
{
    int b = blockIdx.x, d = threadIdx.x;
    float s = 0.f;
    for (int i = 0; i < S; i++) s += o2[((long)b*S + i)*D + d];
    fv[b*D + d] = s*(1.f/S);
}

__global__ void writeloss_k(const float* __restrict__ loss, float* __restrict__ out)
{
    out[0] = loss[0];
}

// ---------------- host -----------------------------------------------------
extern "C" void kernel_launch(void* const* d_in, const int* in_sizes, int n_in,
                              void* d_out, int out_size)
{
    const float* x    = (const float*)d_in[0];
    const float* pe_w = (const float*)d_in[1];
    const float* pe_b = (const float*)d_in[2];
    const float* pos  = (const float*)d_in[3];
    const float* ln1g = (const float*)d_in[4];
    const float* ln1b = (const float*)d_in[5];
    const float* ln2g = (const float*)d_in[6];
    const float* ln2b = (const float*)d_in[7];
    const float* ln3g = (const float*)d_in[8];
    const float* ln3b = (const float*)d_in[9];
    const float* wq = (const float*)d_in[10]; const float* bq = (const float*)d_in[11];
    const float* wk = (const float*)d_in[12]; const float* bk = (const float*)d_in[13];
    const float* wv = (const float*)d_in[14]; const float* bv = (const float*)d_in[15];
    const float* wo = (const float*)d_in[16]; const float* bo = (const float*)d_in[17];
    const float* m1rw = (const float*)d_in[18]; const float* m1rb = (const float*)d_in[19];
    const float* m1w1 = (const float*)d_in[20]; const float* m1b1 = (const float*)d_in[21];
    const float* m1w2 = (const float*)d_in[22]; const float* m1b2 = (const float*)d_in[23];
    const float* m2rw = (const float*)d_in[24]; const float* m2rb = (const float*)d_in[25];
    const float* m2w1 = (const float*)d_in[26]; const float* m2b1 = (const float*)d_in[27];
    const float* m2w2 = (const float*)d_in[28]; const float* m2b2 = (const float*)d_in[29];
    const float* clsw = (const float*)d_in[30]; const float* clsb = (const float*)d_in[31];
    float* out = (float*)d_out;

    float *p_patches, *p_e, *p_ln, *p_q, *p_k, *p_v, *p_kT, *p_attn, *p_av, *p_x2;
    float *p_probs, *p_topv, *p_bgate, *p_hbuf, *p_contrib, *p_o1, *p_o2, *p_loss;
    int *p_topi, *p_btok, *p_slot, *p_eoff, *p_ecnt, *p_ecnt_raw;
    cudaGetSymbolAddress((void**)&p_patches, g_patches);
    cudaGetSymbolAddress((void**)&p_e, g_e);
    cudaGetSymbolAddress((void**)&p_ln, g_ln);
    cudaGetSymbolAddress((void**)&p_q, g_q);
    cudaGetSymbolAddress((void**)&p_k, g_k);
    cudaGetSymbolAddress((void**)&p_v, g_v);
    cudaGetSymbolAddress((void**)&p_kT, g_kT);
    cudaGetSymbolAddress((void**)&p_attn, g_attn);
    cudaGetSymbolAddress((void**)&p_av, g_av);
    cudaGetSymbolAddress((void**)&p_x2, g_x2);
    cudaGetSymbolAddress((void**)&p_probs, g_probs);
    cudaGetSymbolAddress((void**)&p_topv, g_topv);
    cudaGetSymbolAddress((void**)&p_bgate, g_bgate);
    cudaGetSymbolAddress((void**)&p_hbuf, g_hbuf);
    cudaGetSymbolAddress((void**)&p_contrib, g_contrib);
    cudaGetSymbolAddress((void**)&p_o1, g_o1);
    cudaGetSymbolAddress((void**)&p_o2, g_o2);
    cudaGetSymbolAddress((void**)&p_loss, g_loss);
    cudaGetSymbolAddress((void**)&p_topi, g_topi);
    cudaGetSymbolAddress((void**)&p_btok, g_btok);
    cudaGetSymbolAddress((void**)&p_slot, g_slot);
    cudaGetSymbolAddress((void**)&p_eoff, g_eoff);
    cudaGetSymbolAddress((void**)&p_ecnt, g_ecnt);
    cudaGetSymbolAddress((void**)&p_ecnt_raw, g_ecnt_raw);

    // 1. patchify
    {
        long tot = (long)T*PD;
        patchify_k<<<(int)((tot + 255)/256), 256>>>(x, p_patches);
    }
    // 2. embed: e = patches @ pe_w + pe_b + pos
    gemm_k<<<dim3(T/BM, D/BN, 1), 256>>>(p_patches, pe_w, p_e, T, D, PD, PD, D, D,
        0,0,0,0,0,0,1, 1.f, pe_b, 0, pos, nullptr, nullptr, nullptr, nullptr, 2);
    // 3. ln1
    ln_k<<<T*32/256, 256>>>(p_e, ln1g, ln1b, p_ln);
    // 4. q,k,v
    gemm_k<<<dim3(T/BM, D/BN, 1), 256>>>(p_ln, wq, p_q, T, D, D, D, D, D,
        0,0,0,0,0,0,1, 1.f, bq, 0, nullptr, nullptr, nullptr, nullptr, nullptr, 1);
    gemm_k<<<dim3(T/BM, D/BN, 1), 256>>>(p_ln, wk, p_k, T, D, D, D, D, D,
        0,0,0,0,0,0,1, 1.f, bk, 0, nullptr, nullptr, nullptr, nullptr, nullptr, 1);
    gemm_k<<<dim3(T/BM, D/BN, 1), 256>>>(p_ln, wv, p_v, T, D, D, D, D, D,
        0,0,0,0,0,0,1, 1.f, bv, 0, nullptr, nullptr, nullptr, nullptr, nullptr, 1);
    // 5. k transpose
    {
        long tot = (long)Bt*NH*HD*S;
        ktrans_k<<<(int)((tot + 255)/256), 256>>>(p_k, p_kT);
    }
    // 6. scores = q @ kT / 8   (z = b*8 + h)
    gemm_k<<<dim3(S/BM, S/BN, Bt*NH), 256>>>(p_q, p_kT, p_attn, S, S, HD, D, S, S,
        (long)S*D, HD, (long)NH*HD*S, (long)HD*S, (long)NH*S*S, (long)S*S, NH,
        0.125f, nullptr, 0, nullptr, nullptr, nullptr, nullptr, nullptr, 0);
    // 7. softmax rows
    softmax_k<<<Bt*NH*S*32/256, 256>>>(p_attn, Bt*NH*S);
    // 8. attn_w output (head mean + resoftmax) -> d_out + 32769
    attnw_k<<<T*32/256, 256>>>(p_attn, out + 32769);
    // 9. av = attn @ v
    gemm_k<<<dim3(S/BM, 1, Bt*NH), 256>>>(p_attn, p_v, p_av, S, HD, S, S, D, D,
        (long)NH*S*S, (long)S*S, (long)S*D, HD, (long)S*D, HD, NH,
        1.f, nullptr, 0, nullptr, nullptr, nullptr, nullptr, nullptr, 0);
    // 10. out proj + residual: x2 = av @ wo + bo + e
    gemm_k<<<dim3(T/BM, D/BN, 1), 256>>>(p_av, wo, p_x2, T, D, D, D, D, D,
        0,0,0,0,0,0,1, 1.f, bo, 0, p_e, nullptr, nullptr, nullptr, nullptr, 3);

    // ----- MoE layer 1 -----
    ln_k<<<T*32/256, 256>>>(p_x2, ln2g, ln2b, p_ln);
    route_k<<<T*32/256, 256>>>(p_ln, m1rw, m1rb, p_probs, p_topi, p_topv);
    bucket_k<<<1, 256>>>(p_topi, p_topv, p_btok, p_bgate, p_slot, p_eoff, p_ecnt, p_ecnt_raw);
    gemm_k<<<dim3(T*2/BM, HID/BN, E), 256>>>(p_ln, m1w1, p_hbuf, 0, HID, D, D, HID, HID,
        0,0,(long)D*HID,0,0,0,1, 1.f, m1b1, HID, nullptr, p_btok, nullptr, p_eoff, p_ecnt, 4);
    gemm_k<<<dim3(T*2/BM, D/BN, E), 256>>>(p_hbuf, m1w2, p_contrib, 0, D, HID, HID, D, D,
        0,0,(long)HID*D,0,0,0,1, 1.f, m1b2, D, nullptr, nullptr, p_bgate, p_eoff, p_ecnt, 5);
    combine_k<<<T*D/256, 256>>>(p_slot, p_contrib, p_o1);
    loss_k<<<1, 256>>>(p_probs, p_ecnt_raw, p_loss, 0);

    // ----- MoE layer 2 -----
    ln_k<<<T*32/256, 256>>>(p_o1, ln3g, ln3b, p_ln);
    route_k<<<T*32/256, 256>>>(p_ln, m2rw, m2rb, p_probs, p_topi, p_topv);
    bucket_k<<<1, 256>>>(p_topi, p_topv, p_btok, p_bgate, p_slot, p_eoff, p_ecnt, p_ecnt_raw);
    gemm_k<<<dim3(T*2/BM, HID/BN, E), 256>>>(p_ln, m2w1, p_hbuf, 0, HID, D, D, HID, HID,
        0,0,(long)D*HID,0,0,0,1, 1.f, m2b1, HID, nullptr, p_btok, nullptr, p_eoff, p_ecnt, 4);
    gemm_k<<<dim3(T*2/BM, D/BN, E), 256>>>(p_hbuf, m2w2, p_contrib, 0, D, HID, HID, D, D,
        0,0,(long)HID*D,0,0,0,1, 1.f, m2b2, D, nullptr, nullptr, p_bgate, p_eoff, p_ecnt, 5);
    combine_k<<<T*D/256, 256>>>(p_slot, p_contrib, p_o2);
    loss_k<<<1, 256>>>(p_probs, p_ecnt_raw, p_loss, 1);

    // fv = mean(o2, 1) -> d_out + 16384 ; logits = fv @ cls_w + cls_b -> d_out
    fv_k<<<Bt, D>>>(p_o2, out + 16384);
    gemm_k<<<dim3(1, D/BN, 1), 256>>>(out + 16384, clsw, out, Bt, D, D, D, D, D,
        0,0,0,0,0,0,1, 1.f, clsb, 0, nullptr, nullptr, nullptr, nullptr, nullptr, 1);
    // loss scalar
    writeloss_k<<<1, 1>>>(p_loss, out + 32768);
}

// round 5
// speedup vs baseline: 1.3980x; 1.3980x over previous
#include <cuda_runtime.h>
#include <cstdint>
#include <math.h>

#define Bt   32
#define S    256
#define T    8192      // Bt*S
#define D    512
#define PD   588
#define NH   8
#define HD   64
#define E    8
#define HID  2048
#define GBM  128
#define GBN  128
#define GBK  32
#define GTILE 16384
#define NSLOT 17408    // 16384 + 8*128 padding
#define DYNSM 132096   // 2 buffers * 4 tiles * 16KB + 1KB align slack

// ---------------------------------------------------------------------------
// PTX helpers (sm_103a only — guarded at use sites)
// ---------------------------------------------------------------------------
__device__ __forceinline__ uint32_t elect_one_pred() {
    uint32_t pred;
    asm volatile(
        "{\n\t.reg .pred p;\n\telect.sync _|p, 0xFFFFFFFF;\n\t"
        "selp.b32 %0, 1, 0, p;\n\t}" : "=r"(pred));
    return pred;
}
__device__ __forceinline__ uint32_t smem_to_u32(const void* p) {
    uint32_t a;
    asm("{ .reg .u64 t; cvta.to.shared.u64 t, %1; cvt.u32.u64 %0, t; }"
        : "=r"(a) : "l"(p));
    return a;
}
__device__ __forceinline__ float tf32_rna(float x) {
    uint32_t r; asm("cvt.rna.tf32.f32 %0, %1;" : "=r"(r) : "f"(x));
    return __uint_as_float(r);
}

static constexpr uint64_t SMEM_DESC_BASE_SW128 =
    (uint64_t(2)  << 61) | (uint64_t(1) << 46) | (uint64_t(64) << 32) | (uint64_t(1) << 16);
#define MAKE_SMEM_DESC(base_addr) \
    (SMEM_DESC_BASE_SW128 | ((uint64_t)((base_addr) >> 4) & 0x3FFF))

#define TCGEN05_ALLOC(smem_result_addr, nCols) \
    asm volatile("tcgen05.alloc.cta_group::1.sync.aligned.shared::cta.b32 [%0], %1;" \
        :: "r"((uint32_t)(smem_result_addr)), "r"((uint32_t)(nCols)) : "memory")
#define TCGEN05_DEALLOC(tmem_addr, nCols) \
    asm volatile("tcgen05.dealloc.cta_group::1.sync.aligned.b32 %0, %1;" \
        :: "r"(tmem_addr), "r"((uint32_t)(nCols)))
#define TCGEN05_RELINQ() \
    asm volatile("tcgen05.relinquish_alloc_permit.cta_group::1.sync.aligned;")
#define TCGEN05_COMMIT(mbar_smem_addr) \
    asm volatile("tcgen05.commit.cta_group::1.mbarrier::arrive::one.shared::cluster.b64 [%0];" \
        :: "r"((uint32_t)(mbar_smem_addr)) : "memory")
#define TCGEN05_FENCE_AFTER() \
    asm volatile("tcgen05.fence::after_thread_sync;" ::: "memory")
#define TCGEN05_FENCE_BEFORE() \
    asm volatile("tcgen05.fence::before_thread_sync;" ::: "memory")
#define TCGEN05_WAIT_LD() \
    asm volatile("tcgen05.wait::ld.sync.aligned;" ::: "memory")

#define TCGEN05_LD_32X32B_X32(r, tmem_addr) \
    asm volatile( \
        "tcgen05.ld.sync.aligned.32x32b.x32.b32 " \
        "{%0, %1, %2, %3, %4, %5, %6, %7, " \
        " %8, %9, %10, %11, %12, %13, %14, %15, " \
        " %16, %17, %18, %19, %20, %21, %22, %23, " \
        " %24, %25, %26, %27, %28, %29, %30, %31}, [%32];" \
        : "=r"((r)[0]),  "=r"((r)[1]),  "=r"((r)[2]),  "=r"((r)[3]), \
          "=r"((r)[4]),  "=r"((r)[5]),  "=r"((r)[6]),  "=r"((r)[7]), \
          "=r"((r)[8]),  "=r"((r)[9]),  "=r"((r)[10]), "=r"((r)[11]), \
          "=r"((r)[12]), "=r"((r)[13]), "=r"((r)[14]), "=r"((r)[15]), \
          "=r"((r)[16]), "=r"((r)[17]), "=r"((r)[18]), "=r"((r)[19]), \
          "=r"((r)[20]), "=r"((r)[21]), "=r"((r)[22]), "=r"((r)[23]), \
          "=r"((r)[24]), "=r"((r)[25]), "=r"((r)[26]), "=r"((r)[27]), \
          "=r"((r)[28]), "=r"((r)[29]), "=r"((r)[30]), "=r"((r)[31]) \
        : "r"(tmem_addr))

#define MBARRIER_INIT(mbar_smem_addr, count) \
    asm volatile("mbarrier.init.shared.b64 [%0], %1;" \
        :: "r"((uint32_t)(mbar_smem_addr)), "r"((uint32_t)(count)) : "memory")

#define MBARRIER_WAIT_PARITY(mbar_smem_addr, phase_parity) do { \
    uint32_t _mbar = (uint32_t)(mbar_smem_addr); \
    uint32_t _parity = (uint32_t)(phase_parity); \
    uint32_t _done; \
    asm volatile( \
        "{\n\t.reg .pred p;\n\t" \
        "mbarrier.try_wait.parity.acquire.cta.shared::cta.b64 p, [%1], %2;\n\t" \
        "selp.b32 %0, 1, 0, p;\n\t}" \
        : "=r"(_done) : "r"(_mbar), "r"(_parity) : "memory"); \
    if (!_done) { \
        asm volatile( \
            "{\n\t.reg .pred P1;\n\t" \
            "WAIT_LOOP_%=:\n\t" \
            "mbarrier.try_wait.parity.acquire.cta.shared::cta.b64 P1, [%0], %1, 0x989680;\n\t" \
            "@P1 bra.uni WAIT_DONE_%=;\n\t" \
            "bra.uni WAIT_LOOP_%=;\n\t" \
            "WAIT_DONE_%=:\n\t}" \
            :: "r"(_mbar), "r"(_parity) : "memory"); \
    } \
} while(0)

// idesc kind::tf32: dtype=F32(1)<<4 | atype=TF32(2)<<7 | btype=TF32(2)<<10
//                 | (N/8)<<17 | (M/16)<<24  with M=128, N=128
#define IDESC_TF32 0x8200910u

#define TCGEN05_MMA_TF32_SS(d_tmem, a_desc, b_desc, idesc, enable) do { \
    uint32_t _en = (uint32_t)(enable); \
    asm volatile( \
        "{\n\t.reg .pred p;\n\tsetp.ne.u32 p, %5, 0;\n\t" \
        "tcgen05.mma.cta_group::1.kind::tf32 [%0], %1, %2, %3, {%4, %4, %4, %4}, p;\n\t}" \
        :: "r"(d_tmem), "l"(a_desc), "l"(b_desc), "r"(idesc), "r"(0u), "r"(_en) \
        : "memory"); \
} while(0)

// ---------------- scratch -------------------------------------------------
__device__ float g_patches[(long)T*PD];
__device__ float g_e[(long)T*D];
__device__ float g_ln[(long)T*D];
__device__ float g_q[(long)T*D];
__device__ float g_k[(long)T*D];
__device__ float g_v[(long)T*D];
__device__ float g_vT[(long)Bt*NH*HD*S];
__device__ float g_attn[(long)Bt*NH*S*S];
__device__ float g_av[(long)T*D];
__device__ float g_x2[(long)T*D];
__device__ float g_probs[(long)T*E];
__device__ int   g_topi[T*2];
__device__ float g_topv[T*2];
__device__ int   g_btok[NSLOT];
__device__ float g_bgate[NSLOT];
__device__ int   g_slot[T*2];
__device__ int   g_eoff[E];
__device__ int   g_ecnt[E];
__device__ int   g_ecnt_raw[E];
__device__ float g_hbuf[(long)NSLOT*HID];
__device__ float g_contrib[(long)NSLOT*D];
__device__ float g_o1[(long)T*D];
__device__ float g_o2[(long)T*D];
__device__ float g_loss[1];
// transposed weights [N,K]
__device__ float g_pet[(long)D*PD];
__device__ float g_wqt[(long)D*D];
__device__ float g_wkt[(long)D*D];
__device__ float g_wvt[(long)D*D];
__device__ float g_wot[(long)D*D];
__device__ float g_w1t1[(long)E*HID*D];
__device__ float g_w2t1[(long)E*D*HID];
__device__ float g_w1t2[(long)E*HID*D];
__device__ float g_w2t2[(long)E*D*HID];

// ---------------- patchify -------------------------------------------------
__global__ void patchify_k(const float* __restrict__ x, float* __restrict__ out)
{
    long idx = (long)blockIdx.x*blockDim.x + threadIdx.x;
    long total = (long)T*PD;
    if (idx >= total) return;
    int i = idx % PD;
    long r = idx / PD;
    int s = r % S;
    int b = r / S;
    int c  = i % 3;
    int t  = i / 3;
    int p2 = t % 14;
    int p1 = t / 14;
    int hh = s >> 4, ww = s & 15;
    out[idx] = x[(((long)(b*3 + c)*224) + hh*14 + p1)*224 + ww*14 + p2];
}

// ---------------- tiled transpose: in[K,N] -> out[N,K] ---------------------
__global__ void wtrans_k(const float* __restrict__ in, float* __restrict__ out,
                         int K, int N)
{
    __shared__ float t[32][33];
    long zoff = (long)blockIdx.z*K*N;
    int n0 = blockIdx.x*32, k0 = blockIdx.y*32;
    int tx = threadIdx.x, ty = threadIdx.y;
    #pragma unroll
    for (int i = ty; i < 32; i += 8) {
        int k = k0 + i, n = n0 + tx;
        t[i][tx] = (k < K && n < N) ? in[zoff + (long)k*N + n] : 0.f;
    }
    __syncthreads();
    #pragma unroll
    for (int i = ty; i < 32; i += 8) {
        int n = n0 + i, k = k0 + tx;
        if (n < N && k < K) out[zoff + (long)n*K + k] = t[tx][i];
    }
}

// ---------------- tcgen05 tf32 3x-split GEMM -------------------------------
// C[M,N] = A[M,K] @ B[N,K]^T  (both operands K-major), batched via z strides.
// epi: 0 alpha  1 +bias  2 +bias+pos  3 +bias+residual  4 gelu(+bias)  5 gate*(+bias)
__global__ void __launch_bounds__(256, 1) tgemm_k(
    const float* __restrict__ A, const float* __restrict__ B, float* __restrict__ C,
    int M, int N, int K, int lda, int ldb, int ldc,
    long sAo, long sAi, long sBo, long sBi, long sCo, long sCi, int zdiv,
    float alpha, const float* __restrict__ bias, long sBias,
    const float* __restrict__ extra, const int* __restrict__ gatherIdx,
    const float* __restrict__ gates, const int* __restrict__ eoff,
    const int* __restrict__ ecnt, int epi)
{
    extern __shared__ char dynsm[];

    int z = blockIdx.z;
    int zo = z / zdiv, zi = z - zo*zdiv;
    const float* Ab = A + zo*sAo + zi*sAi;
    const float* Bb = B + zo*sBo + zi*sBi;
    float* Cb = C + zo*sCo + zi*sCi;
    int base = 0, Mloc = M;
    if (eoff) { base = eoff[z]; Mloc = (ecnt[z] + GBM - 1) & ~(GBM - 1); }
    int tm = blockIdx.x*GBM;
    if (tm >= Mloc) return;
    int tn = blockIdx.y*GBN;
    const float* biasb = bias ? (bias + (long)z*sBias) : nullptr;

    int tid = threadIdx.x;
    int wid = tid >> 5;

#if defined(__CUDA_ARCH__) && defined(__CUDA_ARCH_FEAT_SM103_ALL)
    // ======================= tcgen05 path (sm_103a) ========================
    __shared__ uint32_t s_tmem;
    __shared__ __align__(8) unsigned long long s_mbar[2];

    char* tb = (char*)(((uintptr_t)dynsm + 1023) & ~(uintptr_t)1023);
    uint32_t tb_u = smem_to_u32(tb);
    uint32_t mbar_u = smem_to_u32(&s_mbar[0]);

    if (tid == 0) { MBARRIER_INIT(mbar_u, 1); MBARRIER_INIT(mbar_u + 8, 1); }
    if (wid == 0) TCGEN05_ALLOC(smem_to_u32(&s_tmem), 128);
    __syncthreads();
    uint32_t tmem = s_tmem;

    const int NC = (K + GBK - 1) / GBK;
    int ph0 = 0, ph1 = 0;

    for (int c = 0; c < NC; c++) {
        int buf = c & 1;
        if (c >= 2) {
            if (buf == 0) { MBARRIER_WAIT_PARITY(mbar_u,     ph0); ph0 ^= 1; }
            else          { MBARRIER_WAIT_PARITY(mbar_u + 8, ph1); ph1 ^= 1; }
        }
        int k0 = c*GBK;
        char* Ah = tb + buf*4*GTILE;
        char* Al = Ah + GTILE;
        char* Bh = Al + GTILE;
        char* Bl = Bh + GTILE;
        #pragma unroll
        for (int t = 0; t < 4; t++) {
            int id = tid + t*256;
            int r = id >> 3, c4 = id & 7;
            int kk = k0 + c4*4;
            uint32_t boff = (uint32_t)(r*128 + c4*16);
            uint32_t sw = boff ^ ((boff >> 3) & 0x70);
            // --- A tile ---
            float4 va = make_float4(0.f, 0.f, 0.f, 0.f);
            if (kk < K) {
                long arow = gatherIdx ? (long)gatherIdx[base + tm + r]
                                      : (long)(base + tm + r);
                va = *(const float4*)(Ab + arow*lda + kk);
            }
            float4 vh, vl;
            vh.x = tf32_rna(va.x); vl.x = va.x - vh.x;
            vh.y = tf32_rna(va.y); vl.y = va.y - vh.y;
            vh.z = tf32_rna(va.z); vl.z = va.z - vh.z;
            vh.w = tf32_rna(va.w); vl.w = va.w - vh.w;
            *(float4*)(Ah + sw) = vh;
            *(float4*)(Al + sw) = vl;
            // --- B tile ---
            float4 vb = make_float4(0.f, 0.f, 0.f, 0.f);
            int gn = tn + r;
            if (kk < K && gn < N)
                vb = *(const float4*)(Bb + (long)gn*ldb + kk);
            vh.x = tf32_rna(vb.x); vl.x = vb.x - vh.x;
            vh.y = tf32_rna(vb.y); vl.y = vb.y - vh.y;
            vh.z = tf32_rna(vb.z); vl.z = vb.z - vh.z;
            vh.w = tf32_rna(vb.w); vl.w = vb.w - vh.w;
            *(float4*)(Bh + sw) = vh;
            *(float4*)(Bl + sw) = vl;
        }
        asm volatile("fence.proxy.async.shared::cta;" ::: "memory");
        __syncthreads();
        if (wid == 0) {
            if (elect_one_pred()) {
                uint32_t au = tb_u + buf*4*GTILE;
                uint64_t dAh = MAKE_SMEM_DESC(au);
                uint64_t dAl = MAKE_SMEM_DESC(au + GTILE);
                uint64_t dBh = MAKE_SMEM_DESC(au + 2*GTILE);
                uint64_t dBl = MAKE_SMEM_DESC(au + 3*GTILE);
                #pragma unroll
                for (int ks = 0; ks < 4; ks++)
                    TCGEN05_MMA_TF32_SS(tmem, dAh + ks*2, dBh + ks*2, IDESC_TF32,
                                        (c > 0) || (ks > 0));
                #pragma unroll
                for (int ks = 0; ks < 4; ks++)
                    TCGEN05_MMA_TF32_SS(tmem, dAh + ks*2, dBl + ks*2, IDESC_TF32, 1);
                #pragma unroll
                for (int ks = 0; ks < 4; ks++)
                    TCGEN05_MMA_TF32_SS(tmem, dAl + ks*2, dBh + ks*2, IDESC_TF32, 1);
                TCGEN05_COMMIT(mbar_u + buf*8);
            }
        }
    }
    {
        int lb = (NC - 1) & 1;
        if (lb == 0) MBARRIER_WAIT_PARITY(mbar_u,     ph0);
        else         MBARRIER_WAIT_PARITY(mbar_u + 8, ph1);
    }
    TCGEN05_FENCE_AFTER();

    if (tid < 128) {
        int row = tm + tid;
        float gate = (epi == 5) ? gates[base + row] : 0.f;
        #pragma unroll 1
        for (int g = 0; g < 4; g++) {
            uint32_t dr[32];
            TCGEN05_LD_32X32B_X32(dr, tmem + g*32);
            TCGEN05_WAIT_LD();
            #pragma unroll
            for (int j = 0; j < 32; j++) {
                int col = tn + g*32 + j;
                if (col < N) {
                    float v = __uint_as_float(dr[j]) * alpha;
                    if (epi >= 1) v += biasb[col];
                    if (epi == 2) v += extra[(long)(row & (S-1))*ldc + col];
                    else if (epi == 3) v += extra[(long)row*ldc + col];
                    else if (epi == 4) v = 0.5f*v*(1.0f + erff(v*0.70710678118654752f));
                    else if (epi == 5) v *= gate;
                    Cb[(long)(base + row)*ldc + col] = v;
                }
            }
        }
        TCGEN05_FENCE_BEFORE();
    }
    __syncthreads();
    if (wid == 0) {
        TCGEN05_RELINQ();
        TCGEN05_DEALLOC(tmem, 128);
    }
#else
    // ============ generic fallback (compute_103 PTX stage only) ============
    // Correct but slow; never executed on sm_103a (exact-SASS is preferred).
    (void)wid; (void)dynsm;
    for (int rc = tid; rc < GBM*GBN; rc += 256) {
        int r = rc >> 7, col0 = rc & 127;
        int row = tm + r;
        int col = tn + col0;
        if (col >= N) continue;
        long arow = gatherIdx ? (long)gatherIdx[base + row] : (long)(base + row);
        const float* ar = Ab + arow*lda;
        const float* br = Bb + (long)col*ldb;
        float acc = 0.f;
        for (int k = 0; k < K; k++) acc = fmaf(ar[k], br[k], acc);
        float v = acc * alpha;
        if (epi >= 1) v += biasb[col];
        if (epi == 2) v += extra[(long)(row & (S-1))*ldc + col];
        else if (epi == 3) v += extra[(long)row*ldc + col];
        else if (epi == 4) v = 0.5f*v*(1.0f + erff(v*0.70710678118654752f));
        else if (epi == 5) v *= gates[base + row];
        Cb[(long)(base + row)*ldc + col] = v;
    }
#endif
}

// ---------------- small FFMA GEMM for the cls head (M=32) ------------------
#define OBM 64
#define OBN 64
#define OBK 16
__global__ void gemm_k(const float* __restrict__ A, const float* __restrict__ B,
                       float* __restrict__ C, int M, int N, int K,
                       int lda, int ldb, int ldc,
                       const float* __restrict__ bias)
{
    __shared__ float As[OBK][OBM];
    __shared__ float Bs[OBK][OBN+4];
    int tm = blockIdx.x*OBM;
    int tn = blockIdx.y*OBN;
    int tid = threadIdx.x;
    int tx = tid & 15, ty = tid >> 4;
    float acc[4][4] = {};
    for (int k0 = 0; k0 < K; k0 += OBK) {
        #pragma unroll
        for (int t = 0; t < 4; t++) {
            int id = tid + t*256;
            int r = id >> 4, c = id & 15;
            int gr = tm + r;
            float v = 0.f;
            if (gr < M && (k0 + c) < K) v = A[(long)gr*lda + k0 + c];
            As[c][r] = v;
        }
        #pragma unroll
        for (int t = 0; t < 4; t++) {
            int id = tid + t*256;
            int r = id >> 6, c = id & 63;
            float v = 0.f;
            if ((k0 + r) < K && (tn + c) < N) v = B[(long)(k0 + r)*ldb + tn + c];
            Bs[r][c] = v;
        }
        __syncthreads();
        #pragma unroll
        for (int kk = 0; kk < OBK; kk++) {
            float av[4], bv[4];
            #pragma unroll
            for (int i = 0; i < 4; i++) av[i] = As[kk][ty*4 + i];
            #pragma unroll
            for (int j = 0; j < 4; j++) bv[j] = Bs[kk][tx*4 + j];
            #pragma unroll
            for (int i = 0; i < 4; i++)
                #pragma unroll
                for (int j = 0; j < 4; j++)
                    acc[i][j] = fmaf(av[i], bv[j], acc[i][j]);
        }
        __syncthreads();
    }
    #pragma unroll
    for (int i = 0; i < 4; i++) {
        int row = tm + ty*4 + i;
        if (row >= M) continue;
        #pragma unroll
        for (int j = 0; j < 4; j++) {
            int col = tn + tx*4 + j;
            if (col >= N) continue;
            C[(long)row*ldc + col] = acc[i][j] + bias[col];
        }
    }
}

// ---------------- layernorm ------------------------------------------------
__global__ void ln_k(const float* __restrict__ x, const float* __restrict__ g,
                     const float* __restrict__ b, float* __restrict__ y)
{
    int row  = (blockIdx.x*blockDim.x + threadIdx.x) >> 5;
    int lane = threadIdx.x & 31;
    if (row >= T) return;
    const float* xr = x + (long)row*D;
    float v[16]; float s = 0.f;
    #pragma unroll
    for (int i = 0; i < 16; i++) { v[i] = xr[lane + 32*i]; s += v[i]; }
    #pragma unroll
    for (int o = 16; o > 0; o >>= 1) s += __shfl_xor_sync(~0u, s, o);
    float mean = s*(1.f/D);
    float vs = 0.f;
    #pragma unroll
    for (int i = 0; i < 16; i++) { float d = v[i]-mean; vs += d*d; }
    #pragma unroll
    for (int o = 16; o > 0; o >>= 1) vs += __shfl_xor_sync(~0u, vs, o);
    float rstd = rsqrtf(vs*(1.f/D) + 1e-5f);
    float* yr = y + (long)row*D;
    #pragma unroll
    for (int i = 0; i < 16; i++) { int c = lane + 32*i; yr[c] = (v[i]-mean)*rstd*g[c] + b[c]; }
}

// ---------------- v transpose: [t, h*64+d] -> [(b*8+h)*64+d][j] ------------
__global__ void ktrans_k(const float* __restrict__ k, float* __restrict__ kT)
{
    long idx = (long)blockIdx.x*blockDim.x + threadIdx.x;
    long total = (long)Bt*NH*HD*S;
    if (idx >= total) return;
    int j = idx & 255; long r = idx >> 8;
    int d = r & 63; r >>= 6;
    int h = r & 7; int b = (int)(r >> 3);
    kT[idx] = k[((long)(b*S + j))*D + h*HD + d];
}

// ---------------- softmax over last dim (256) ------------------------------
__global__ void softmax_k(float* __restrict__ a, int rows)
{
    int row  = (blockIdx.x*blockDim.x + threadIdx.x) >> 5;
    int lane = threadIdx.x & 31;
    if (row >= rows) return;
    float* r = a + (long)row*S;
    float v[8]; float m = -1e30f;
    #pragma unroll
    for (int i = 0; i < 8; i++) { v[i] = r[lane + 32*i]; m = fmaxf(m, v[i]); }
    #pragma unroll
    for (int o = 16; o > 0; o >>= 1) m = fmaxf(m, __shfl_xor_sync(~0u, m, o));
    float s = 0.f;
    #pragma unroll
    for (int i = 0; i < 8; i++) { v[i] = expf(v[i]-m); s += v[i]; }
    #pragma unroll
    for (int o = 16; o > 0; o >>= 1) s += __shfl_xor_sync(~0u, s, o);
    float inv = 1.f/s;
    #pragma unroll
    for (int i = 0; i < 8; i++) r[lane + 32*i] = v[i]*inv;
}

// ---------------- head-mean + re-softmax -> attn_w -------------------------
__global__ void attnw_k(const float* __restrict__ attn, float* __restrict__ out)
{
    int row  = (blockIdx.x*blockDim.x + threadIdx.x) >> 5;
    int lane = threadIdx.x & 31;
    if (row >= T) return;
    int b = row >> 8, i = row & 255;
    const float* base = attn + ((long)b*NH*S + i)*S;
    float v[8];
    #pragma unroll
    for (int t = 0; t < 8; t++) {
        int j = lane + 32*t; float s = 0.f;
        #pragma unroll
        for (int h = 0; h < NH; h++) s += base[(long)h*S*S + j];
        v[t] = s*0.125f;
    }
    float m = -1e30f;
    #pragma unroll
    for (int t = 0; t < 8; t++) m = fmaxf(m, v[t]);
    #pragma unroll
    for (int o = 16; o > 0; o >>= 1) m = fmaxf(m, __shfl_xor_sync(~0u, m, o));
    float s = 0.f;
    #pragma unroll
    for (int t = 0; t < 8; t++) { v[t] = expf(v[t]-m); s += v[t]; }
    #pragma unroll
    for (int o = 16; o > 0; o >>= 1) s += __shfl_xor_sync(~0u, s, o);
    float inv = 1.f/s;
    float* orow = out + (long)row*S;
    #pragma unroll
    for (int t = 0; t < 8; t++) orow[lane + 32*t] = v[t]*inv;
}

// ---------------- MoE routing ----------------------------------------------
__global__ void route_k(const float* __restrict__ xln, const float* __restrict__ rw,
                        const float* __restrict__ rb, float* __restrict__ probs,
                        int* __restrict__ topi, float* __restrict__ topv)
{
    int tok  = (blockIdx.x*blockDim.x + threadIdx.x) >> 5;
    int lane = threadIdx.x & 31;
    if (tok >= T) return;
    const float* xr = xln + (long)tok*D;
    float acc[E] = {};
    for (int d = lane; d < D; d += 32) {
        float xv = xr[d];
        #pragma unroll
        for (int e = 0; e < E; e++) acc[e] = fmaf(xv, rw[d*E + e], acc[e]);
    }
    #pragma unroll
    for (int e = 0; e < E; e++)
        #pragma unroll
        for (int o = 16; o > 0; o >>= 1) acc[e] += __shfl_xor_sync(~0u, acc[e], o);
    if (lane == 0) {
        float mx = -1e30f;
        #pragma unroll
        for (int e = 0; e < E; e++) { acc[e] += rb[e]; mx = fmaxf(mx, acc[e]); }
        float s = 0.f, p[E];
        #pragma unroll
        for (int e = 0; e < E; e++) { p[e] = expf(acc[e]-mx); s += p[e]; }
        float inv = 1.f/s;
        int i0 = 0; float v0 = -1.f;
        #pragma unroll
        for (int e = 0; e < E; e++) { p[e] *= inv; probs[(long)tok*E + e] = p[e];
                                      if (p[e] > v0) { v0 = p[e]; i0 = e; } }
        int i1 = 0; float v1 = -1.f;
        #pragma unroll
        for (int e = 0; e < E; e++) { if (e != i0 && p[e] > v1) { v1 = p[e]; i1 = e; } }
        topi[tok*2] = i0;  topv[tok*2] = v0;
        topi[tok*2+1] = i1; topv[tok*2+1] = v1;
    }
}

// ---------------- bucket build (single block, pad to 128) ------------------
__global__ void bucket_k(const int* __restrict__ topi, const float* __restrict__ topv,
                         int* __restrict__ btok, float* __restrict__ bgate,
                         int* __restrict__ slot, int* __restrict__ eoff,
                         int* __restrict__ ecnt, int* __restrict__ ecnt_raw)
{
    __shared__ int cnt[E], off[E], cur[E];
    int tid = threadIdx.x;
    if (tid < E) cnt[tid] = 0;
    __syncthreads();
    for (int t = tid; t < T; t += 256) {
        atomicAdd(&cnt[topi[t*2]], 1);
        atomicAdd(&cnt[topi[t*2+1]], 1);
    }
    __syncthreads();
    if (tid == 0) {
        int o = 0;
        for (int e = 0; e < E; e++) { off[e] = o; o += (cnt[e] + GBM - 1) & ~(GBM - 1); }
    }
    __syncthreads();
    if (tid < E) {
        cur[tid] = off[tid];
        eoff[tid] = off[tid];
        ecnt[tid] = cnt[tid];
        ecnt_raw[tid] = cnt[tid];
    }
    __syncthreads();
    for (int t = tid; t < T; t += 256) {
        #pragma unroll
        for (int k = 0; k < 2; k++) {
            int e = topi[t*2 + k];
            int pos = atomicAdd(&cur[e], 1);
            btok[pos] = t;
            bgate[pos] = topv[t*2 + k];
            slot[t*2 + k] = pos;
        }
    }
    __syncthreads();
    for (int e = 0; e < E; e++) {
        int start = off[e] + cnt[e];
        int end   = off[e] + ((cnt[e] + GBM - 1) & ~(GBM - 1));
        for (int p = start + tid; p < end; p += 256) { btok[p] = 0; bgate[p] = 0.f; }
    }
}

// ---------------- combine 2 slot contributions -----------------------------
__global__ void combine_k(const int* __restrict__ slot, const float* __restrict__ contrib,
                          float* __restrict__ out)
{
    long idx = (long)blockIdx.x*blockDim.x + threadIdx.x;
    if (idx >= (long)T*D) return;
    int t = (int)(idx >> 9), d = (int)(idx & 511);
    int s0 = slot[t*2], s1 = slot[t*2+1];
    out[idx] = contrib[(long)s0*D + d] + contrib[(long)s1*D + d];
}

// ---------------- aux loss -------------------------------------------------
__global__ void loss_k(const float* __restrict__ probs, const int* __restrict__ ecnt_raw,
                       float* __restrict__ out, int accum)
{
    __shared__ float red[256*E];
    int tid = threadIdx.x;
    float acc[E] = {};
    for (int t = tid; t < T; t += 256)
        #pragma unroll
        for (int e = 0; e < E; e++) acc[e] += probs[(long)t*E + e];
    #pragma unroll
    for (int e = 0; e < E; e++) red[tid*E + e] = acc[e];
    __syncthreads();
    for (int s = 128; s > 0; s >>= 1) {
        if (tid < s)
            #pragma unroll
            for (int e = 0; e < E; e++) red[tid*E + e] += red[(tid + s)*E + e];
        __syncthreads();
    }
    if (tid == 0) {
        float l = 0.f;
        for (int e = 0; e < E; e++) {
            float imp  = red[e]*(1.f/T);
            float frac = (float)ecnt_raw[e]*(1.f/T);
            l += frac*imp;
        }
        l *= (float)E;
        if (accum) out[0] += l; else out[0] = l;
    }
}

// ---------------- fv mean over S -------------------------------------------
__global__ void fv_k(const float* __restrict__ o2, float* __restrict__ fv)
{
    int b = blockIdx.x, d = threadIdx.x;
    float s = 0.f;
    for (int i = 0; i < S; i++) s += o2[((long)b*S + i)*D + d];
    fv[b*D + d] = s*(1.f/S);
}

__global__ void writeloss_k(const float* __restrict__ loss, float* __restrict__ out)
{
    out[0] = loss[0];
}

// ---------------- host -----------------------------------------------------
extern "C" void kernel_launch(void* const* d_in, const int* in_sizes, int n_in,
                              void* d_out, int out_size)
{
    const float* x    = (const float*)d_in[0];
    const float* pe_w = (const float*)d_in[1];
    const float* pe_b = (const float*)d_in[2];
    const float* pos  = (const float*)d_in[3];
    const float* ln1g = (const float*)d_in[4];
    const float* ln1b = (const float*)d_in[5];
    const float* ln2g = (const float*)d_in[6];
    const float* ln2b = (const float*)d_in[7];
    const float* ln3g = (const float*)d_in[8];
    const float* ln3b = (const float*)d_in[9];
    const float* wq = (const float*)d_in[10]; const float* bq = (const float*)d_in[11];
    const float* wk = (const float*)d_in[12]; const float* bk = (const float*)d_in[13];
    const float* wv = (const float*)d_in[14]; const float* bv = (const float*)d_in[15];
    const float* wo = (const float*)d_in[16]; const float* bo = (const float*)d_in[17];
    const float* m1rw = (const float*)d_in[18]; const float* m1rb = (const float*)d_in[19];
    const float* m1w1 = (const float*)d_in[20]; const float* m1b1 = (const float*)d_in[21];
    const float* m1w2 = (const float*)d_in[22]; const float* m1b2 = (const float*)d_in[23];
    const float* m2rw = (const float*)d_in[24]; const float* m2rb = (const float*)d_in[25];
    const float* m2w1 = (const float*)d_in[26]; const float* m2b1 = (const float*)d_in[27];
    const float* m2w2 = (const float*)d_in[28]; const float* m2b2 = (const float*)d_in[29];
    const float* clsw = (const float*)d_in[30]; const float* clsb = (const float*)d_in[31];
    float* out = (float*)d_out;

    cudaFuncSetAttribute(tgemm_k, cudaFuncAttributeMaxDynamicSharedMemorySize, DYNSM);

    float *p_patches, *p_e, *p_ln, *p_q, *p_k, *p_v, *p_vT, *p_attn, *p_av, *p_x2;
    float *p_probs, *p_topv, *p_bgate, *p_hbuf, *p_contrib, *p_o1, *p_o2, *p_loss;
    float *p_pet, *p_wqt, *p_wkt, *p_wvt, *p_wot, *p_w1t1, *p_w2t1, *p_w1t2, *p_w2t2;
    int *p_topi, *p_btok, *p_slot, *p_eoff, *p_ecnt, *p_ecnt_raw;
    cudaGetSymbolAddress((void**)&p_patches, g_patches);
    cudaGetSymbolAddress((void**)&p_e, g_e);
    cudaGetSymbolAddress((void**)&p_ln, g_ln);
    cudaGetSymbolAddress((void**)&p_q, g_q);
    cudaGetSymbolAddress((void**)&p_k, g_k);
    cudaGetSymbolAddress((void**)&p_v, g_v);
    cudaGetSymbolAddress((void**)&p_vT, g_vT);
    cudaGetSymbolAddress((void**)&p_attn, g_attn);
    cudaGetSymbolAddress((void**)&p_av, g_av);
    cudaGetSymbolAddress((void**)&p_x2, g_x2);
    cudaGetSymbolAddress((void**)&p_probs, g_probs);
    cudaGetSymbolAddress((void**)&p_topv, g_topv);
    cudaGetSymbolAddress((void**)&p_bgate, g_bgate);
    cudaGetSymbolAddress((void**)&p_hbuf, g_hbuf);
    cudaGetSymbolAddress((void**)&p_contrib, g_contrib);
    cudaGetSymbolAddress((void**)&p_o1, g_o1);
    cudaGetSymbolAddress((void**)&p_o2, g_o2);
    cudaGetSymbolAddress((void**)&p_loss, g_loss);
    cudaGetSymbolAddress((void**)&p_topi, g_topi);
    cudaGetSymbolAddress((void**)&p_btok, g_btok);
    cudaGetSymbolAddress((void**)&p_slot, g_slot);
    cudaGetSymbolAddress((void**)&p_eoff, g_eoff);
    cudaGetSymbolAddress((void**)&p_ecnt, g_ecnt);
    cudaGetSymbolAddress((void**)&p_ecnt_raw, g_ecnt_raw);
    cudaGetSymbolAddress((void**)&p_pet, g_pet);
    cudaGetSymbolAddress((void**)&p_wqt, g_wqt);
    cudaGetSymbolAddress((void**)&p_wkt, g_wkt);
    cudaGetSymbolAddress((void**)&p_wvt, g_wvt);
    cudaGetSymbolAddress((void**)&p_wot, g_wot);
    cudaGetSymbolAddress((void**)&p_w1t1, g_w1t1);
    cudaGetSymbolAddress((void**)&p_w2t1, g_w2t1);
    cudaGetSymbolAddress((void**)&p_w1t2, g_w1t2);
    cudaGetSymbolAddress((void**)&p_w2t2, g_w2t2);

    dim3 tt(32, 8);
    // weight transposes: in[K,N] -> out[N,K]
    wtrans_k<<<dim3(16, 19, 1), tt>>>(pe_w, p_pet, PD, D);
    wtrans_k<<<dim3(16, 16, 1), tt>>>(wq, p_wqt, D, D);
    wtrans_k<<<dim3(16, 16, 1), tt>>>(wk, p_wkt, D, D);
    wtrans_k<<<dim3(16, 16, 1), tt>>>(wv, p_wvt, D, D);
    wtrans_k<<<dim3(16, 16, 1), tt>>>(wo, p_wot, D, D);
    wtrans_k<<<dim3(64, 16, E), tt>>>(m1w1, p_w1t1, D, HID);
    wtrans_k<<<dim3(16, 64, E), tt>>>(m1w2, p_w2t1, HID, D);
    wtrans_k<<<dim3(64, 16, E), tt>>>(m2w1, p_w1t2, D, HID);
    wtrans_k<<<dim3(16, 64, E), tt>>>(m2w2, p_w2t2, HID, D);

    // patchify + embed
    {
        long tot = (long)T*PD;
        patchify_k<<<(int)((tot + 255)/256), 256>>>(x, p_patches);
    }
    tgemm_k<<<dim3(T/GBM, D/GBN, 1), 256, DYNSM>>>(p_patches, p_pet, p_e, T, D, PD,
        PD, PD, D, 0,0,0,0,0,0,1, 1.f, pe_b, 0, pos, nullptr, nullptr, nullptr, nullptr, 2);
    ln_k<<<T*32/256, 256>>>(p_e, ln1g, ln1b, p_ln);

    // qkv
    tgemm_k<<<dim3(T/GBM, D/GBN, 1), 256, DYNSM>>>(p_ln, p_wqt, p_q, T, D, D,
        D, D, D, 0,0,0,0,0,0,1, 1.f, bq, 0, nullptr, nullptr, nullptr, nullptr, nullptr, 1);
    tgemm_k<<<dim3(T/GBM, D/GBN, 1), 256, DYNSM>>>(p_ln, p_wkt, p_k, T, D, D,
        D, D, D, 0,0,0,0,0,0,1, 1.f, bk, 0, nullptr, nullptr, nullptr, nullptr, nullptr, 1);
    tgemm_k<<<dim3(T/GBM, D/GBN, 1), 256, DYNSM>>>(p_ln, p_wvt, p_v, T, D, D,
        D, D, D, 0,0,0,0,0,0,1, 1.f, bv, 0, nullptr, nullptr, nullptr, nullptr, nullptr, 1);
    {
        long tot = (long)Bt*NH*HD*S;
        ktrans_k<<<(int)((tot + 255)/256), 256>>>(p_v, p_vT);
    }
    // scores = q @ k^T / 8 ; A=q[per b,h], B=k rows (K-major)
    tgemm_k<<<dim3(2, 2, Bt*NH), 256, DYNSM>>>(p_q, p_k, p_attn, S, S, HD,
        D, D, S, (long)S*D, HD, (long)S*D, HD, (long)NH*S*S, (long)S*S, NH,
        0.125f, nullptr, 0, nullptr, nullptr, nullptr, nullptr, nullptr, 0);
    softmax_k<<<Bt*NH*S*32/256, 256>>>(p_attn, Bt*NH*S);
    attnw_k<<<T*32/256, 256>>>(p_attn, out + 32769);
    // av = attn @ v ; B = vT (rows=d, K=j)
    tgemm_k<<<dim3(2, 1, Bt*NH), 256, DYNSM>>>(p_attn, p_vT, p_av, S, HD, S,
        S, S, D, (long)NH*S*S, (long)S*S, (long)NH*HD*S, (long)HD*S, (long)S*D, HD, NH,
        1.f, nullptr, 0, nullptr, nullptr, nullptr, nullptr, nullptr, 0);
    // out proj + residual
    tgemm_k<<<dim3(T/GBM, D/GBN, 1), 256, DYNSM>>>(p_av, p_wot, p_x2, T, D, D,
        D, D, D, 0,0,0,0,0,0,1, 1.f, bo, 0, p_e, nullptr, nullptr, nullptr, nullptr, 3);

    // ----- MoE layer 1 -----
    ln_k<<<T*32/256, 256>>>(p_x2, ln2g, ln2b, p_ln);
    route_k<<<T*32/256, 256>>>(p_ln, m1rw, m1rb, p_probs, p_topi, p_topv);
    bucket_k<<<1, 256>>>(p_topi, p_topv, p_btok, p_bgate, p_slot, p_eoff, p_ecnt, p_ecnt_raw);
    tgemm_k<<<dim3(128, HID/GBN, E), 256, DYNSM>>>(p_ln, p_w1t1, p_hbuf, 0, HID, D,
        D, D, HID, 0,0,(long)HID*D,0,0,0,1, 1.f, m1b1, HID, nullptr, p_btok, nullptr,
        p_eoff, p_ecnt, 4);
    tgemm_k<<<dim3(128, D/GBN, E), 256, DYNSM>>>(p_hbuf, p_w2t1, p_contrib, 0, D, HID,
        HID, HID, D, 0,0,(long)HID*D,0,0,0,1, 1.f, m1b2, D, nullptr, nullptr, p_bgate,
        p_eoff, p_ecnt, 5);
    combine_k<<<T*D/256, 256>>>(p_slot, p_contrib, p_o1);
    loss_k<<<1, 256>>>(p_probs, p_ecnt_raw, p_loss, 0);

    // ----- MoE layer 2 -----
    ln_k<<<T*32/256, 256>>>(p_o1, ln3g, ln3b, p_ln);
    route_k<<<T*32/256, 256>>>(p_ln, m2rw, m2rb, p_probs, p_topi, p_topv);
    bucket_k<<<1, 256>>>(p_topi, p_topv, p_btok, p_bgate, p_slot, p_eoff, p_ecnt, p_ecnt_raw);
    tgemm_k<<<dim3(128, HID/GBN, E), 256, DYNSM>>>(p_ln, p_w1t2, p_hbuf, 0, HID, D,
        D, D, HID, 0,0,(long)HID*D,0,0,0,1, 1.f, m2b1, HID, nullptr, p_btok, nullptr,
        p_eoff, p_ecnt, 4);
    tgemm_k<<<dim3(128, D/GBN, E), 256, DYNSM>>>(p_hbuf, p_w2t2, p_contrib, 0, D, HID,
        HID, HID, D, 0,0,(long)HID*D,0,0,0,1, 1.f, m2b2, D, nullptr, nullptr, p_bgate,
        p_eoff, p_ecnt, 5);
    combine_k<<<T*D/256, 256>>>(p_slot, p_contrib, p_o2);
    loss_k<<<1, 256>>>(p_probs, p_ecnt_raw, p_loss, 1);

    // fv, logits, loss
    fv_k<<<Bt, D>>>(p_o2, out + 16384);
    gemm_k<<<dim3(1, D/OBN, 1), 256>>>(out + 16384, clsw, out, Bt, D, D, D, D, D, clsb);
    writeloss_k<<<1, 1>>>(p_loss, out + 32768);
}

// round 8
// speedup vs baseline: 4.6961x; 3.3591x over previous
#include <cuda_runtime.h>
#include <cuda_bf16.h>
#include <cstdint>
#include <math.h>

#define Bt   32
#define S    256
#define T    8192      // Bt*S
#define D    512
#define PD   588
#define PDK  640       // PD padded to multiple of 64
#define NH   8
#define HD   64
#define E    8
#define HID  2048
#define GBM  128
#define GBN  128
#define GBK  64
#define GTILE 16384    // 128 rows * 128 bytes (bf16 64-wide)
#define NSLOT 17408
#define DYNSM 132096   // 2 bufs * 4 tiles * 16KB + align slack

typedef __nv_bfloat16 bf16;

// ---------------------------------------------------------------------------
// PTX helpers
// ---------------------------------------------------------------------------
__device__ __forceinline__ uint32_t elect_one_pred() {
    uint32_t pred;
    asm volatile(
        "{\n\t.reg .pred p;\n\telect.sync _|p, 0xFFFFFFFF;\n\t"
        "selp.b32 %0, 1, 0, p;\n\t}" : "=r"(pred));
    return pred;
}
__device__ __forceinline__ uint32_t smem_to_u32(const void* p) {
    uint32_t a;
    asm("{ .reg .u64 t; cvta.to.shared.u64 t, %1; cvt.u32.u64 %0, t; }"
        : "=r"(a) : "l"(p));
    return a;
}

static constexpr uint64_t SMEM_DESC_BASE_SW128 =
    (uint64_t(2)  << 61) | (uint64_t(1) << 46) | (uint64_t(64) << 32) | (uint64_t(1) << 16);
#define MAKE_SMEM_DESC(base_addr) \
    (SMEM_DESC_BASE_SW128 | ((uint64_t)((base_addr) >> 4) & 0x3FFF))

#define TCGEN05_ALLOC(smem_result_addr, nCols) \
    asm volatile("tcgen05.alloc.cta_group::1.sync.aligned.shared::cta.b32 [%0], %1;" \
        :: "r"((uint32_t)(smem_result_addr)), "r"((uint32_t)(nCols)) : "memory")
#define TCGEN05_DEALLOC(tmem_addr, nCols) \
    asm volatile("tcgen05.dealloc.cta_group::1.sync.aligned.b32 %0, %1;" \
        :: "r"(tmem_addr), "r"((uint32_t)(nCols)))
#define TCGEN05_RELINQ() \
    asm volatile("tcgen05.relinquish_alloc_permit.cta_group::1.sync.aligned;")
#define TCGEN05_COMMIT(mbar_smem_addr) \
    asm volatile("tcgen05.commit.cta_group::1.mbarrier::arrive::one.shared::cluster.b64 [%0];" \
        :: "r"((uint32_t)(mbar_smem_addr)) : "memory")
#define TCGEN05_FENCE_AFTER() \
    asm volatile("tcgen05.fence::after_thread_sync;" ::: "memory")
#define TCGEN05_FENCE_BEFORE() \
    asm volatile("tcgen05.fence::before_thread_sync;" ::: "memory")
#define TCGEN05_WAIT_LD() \
    asm volatile("tcgen05.wait::ld.sync.aligned;" ::: "memory")

#define TCGEN05_LD_32X32B_X32(r, tmem_addr) \
    asm volatile( \
        "tcgen05.ld.sync.aligned.32x32b.x32.b32 " \
        "{%0, %1, %2, %3, %4, %5, %6, %7, " \
        " %8, %9, %10, %11, %12, %13, %14, %15, " \
        " %16, %17, %18, %19, %20, %21, %22, %23, " \
        " %24, %25, %26, %27, %28, %29, %30, %31}, [%32];" \
        : "=r"((r)[0]),  "=r"((r)[1]),  "=r"((r)[2]),  "=r"((r)[3]), \
          "=r"((r)[4]),  "=r"((r)[5]),  "=r"((r)[6]),  "=r"((r)[7]), \
          "=r"((r)[8]),  "=r"((r)[9]),  "=r"((r)[10]), "=r"((r)[11]), \
          "=r"((r)[12]), "=r"((r)[13]), "=r"((r)[14]), "=r"((r)[15]), \
          "=r"((r)[16]), "=r"((r)[17]), "=r"((r)[18]), "=r"((r)[19]), \
          "=r"((r)[20]), "=r"((r)[21]), "=r"((r)[22]), "=r"((r)[23]), \
          "=r"((r)[24]), "=r"((r)[25]), "=r"((r)[26]), "=r"((r)[27]), \
          "=r"((r)[28]), "=r"((r)[29]), "=r"((r)[30]), "=r"((r)[31]) \
        : "r"(tmem_addr))

#define MBARRIER_INIT(mbar_smem_addr, count) \
    asm volatile("mbarrier.init.shared.b64 [%0], %1;" \
        :: "r"((uint32_t)(mbar_smem_addr)), "r"((uint32_t)(count)) : "memory")

#define MBARRIER_WAIT_PARITY(mbar_smem_addr, phase_parity) do { \
    uint32_t _mbar = (uint32_t)(mbar_smem_addr); \
    uint32_t _parity = (uint32_t)(phase_parity); \
    uint32_t _done; \
    asm volatile( \
        "{\n\t.reg .pred p;\n\t" \
        "mbarrier.try_wait.parity.acquire.cta.shared::cta.b64 p, [%1], %2;\n\t" \
        "selp.b32 %0, 1, 0, p;\n\t}" \
        : "=r"(_done) : "r"(_mbar), "r"(_parity) : "memory"); \
    if (!_done) { \
        asm volatile( \
            "{\n\t.reg .pred P1;\n\t" \
            "WAIT_LOOP_%=:\n\t" \
            "mbarrier.try_wait.parity.acquire.cta.shared::cta.b64 P1, [%0], %1, 0x989680;\n\t" \
            "@P1 bra.uni WAIT_DONE_%=;\n\t" \
            "bra.uni WAIT_LOOP_%=;\n\t" \
            "WAIT_DONE_%=:\n\t}" \
            :: "r"(_mbar), "r"(_parity) : "memory"); \
    } \
} while(0)

#define CP_ASYNC16(dst_u32, src_ptr) \
    asm volatile("cp.async.cg.shared.global [%0], [%1], 16;" \
        :: "r"((uint32_t)(dst_u32)), "l"(src_ptr) : "memory")
#define CP_COMMIT() asm volatile("cp.async.commit_group;" ::: "memory")
#define CP_WAIT0()  asm volatile("cp.async.wait_group 0;" ::: "memory")

// idesc kind::f16 (bf16): F32(1)<<4 | BF16(1)<<7 | BF16(1)<<10 | (N/8)<<17 | (M/16)<<24
#define IDESC_BF16 0x8200490u

#define TCGEN05_MMA_BF16_SS(d_tmem, a_desc, b_desc, enable) do { \
    uint32_t _en = (uint32_t)(enable); \
    asm volatile( \
        "{\n\t.reg .pred p;\n\tsetp.ne.u32 p, %5, 0;\n\t" \
        "tcgen05.mma.cta_group::1.kind::f16 [%0], %1, %2, %3, {%4, %4, %4, %4}, p;\n\t}" \
        :: "r"(d_tmem), "l"(a_desc), "l"(b_desc), "r"(IDESC_BF16), "r"(0u), "r"(_en) \
        : "memory"); \
} while(0)

__device__ __forceinline__ void split_bf16(float x, bf16& h, bf16& l) {
    h = __float2bfloat16(x);
    l = __float2bfloat16(x - __bfloat162float(h));
}

// ---------------- scratch ---------------------------------------------------
__device__ float g_e[(long)T*D];
__device__ float g_ln[(long)T*D];
__device__ float g_v[(long)T*D];
__device__ float g_attn[(long)Bt*NH*S*S];
__device__ float g_x2[(long)T*D];
__device__ float g_contrib[(long)NSLOT*D];
__device__ float g_o1[(long)T*D];
__device__ float g_o2[(long)T*D];
__device__ float g_probs[(long)T*E];
__device__ int   g_topi[T*2];
__device__ float g_topv[T*2];
__device__ int   g_btok[NSLOT];
__device__ float g_bgate[NSLOT];
__device__ int   g_slot[T*2];
__device__ int   g_eoff[E];
__device__ int   g_ecnt[E];
__device__ int   g_ecnt_raw[E];
__device__ float g_loss[1];
// split-bf16 activations
__device__ bf16 g_patH[(long)T*PDK],  g_patL[(long)T*PDK];
__device__ bf16 g_lnH[(long)T*D],     g_lnL[(long)T*D];
__device__ bf16 g_qH[(long)T*D],      g_qL[(long)T*D];
__device__ bf16 g_kH[(long)T*D],      g_kL[(long)T*D];
__device__ bf16 g_vTH[(long)Bt*NH*HD*S], g_vTL[(long)Bt*NH*HD*S];
__device__ bf16 g_attnH[(long)Bt*NH*S*S], g_attnL[(long)Bt*NH*S*S];
__device__ bf16 g_avH[(long)T*D],     g_avL[(long)T*D];
__device__ bf16 g_hbufH[(long)NSLOT*HID], g_hbufL[(long)NSLOT*HID];
// split-bf16 transposed weights [N,K]
__device__ bf16 g_petH[(long)D*PDK],  g_petL[(long)D*PDK];
__device__ bf16 g_wqtH[(long)D*D],    g_wqtL[(long)D*D];
__device__ bf16 g_wktH[(long)D*D],    g_wktL[(long)D*D];
__device__ bf16 g_wvtH[(long)D*D],    g_wvtL[(long)D*D];
__device__ bf16 g_wotH[(long)D*D],    g_wotL[(long)D*D];
__device__ bf16 g_w1t1H[(long)E*HID*D], g_w1t1L[(long)E*HID*D];
__device__ bf16 g_w2t1H[(long)E*D*HID], g_w2t1L[(long)E*D*HID];
__device__ bf16 g_w1t2H[(long)E*HID*D], g_w1t2L[(long)E*HID*D];
__device__ bf16 g_w2t2H[(long)E*D*HID], g_w2t2L[(long)E*D*HID];

// ---------------- patchify (writes split directly, K padded) ----------------
__global__ void patchify_k(const float* __restrict__ x,
                           bf16* __restrict__ oh, bf16* __restrict__ ol)
{
    long idx = (long)blockIdx.x*blockDim.x + threadIdx.x;
    long total = (long)T*PDK;
    if (idx >= total) return;
    int i = idx % PDK;
    long r = idx / PDK;
    float v = 0.f;
    if (i < PD) {
        int s = r % S;
        int b = r / S;
        int c  = i % 3;
        int t  = i / 3;
        int p2 = t % 14;
        int p1 = t / 14;
        int hh = s >> 4, ww = s & 15;
        v = x[(((long)(b*3 + c)*224) + hh*14 + p1)*224 + ww*14 + p2];
    }
    bf16 h, l; split_bf16(v, h, l);
    oh[idx] = h; ol[idx] = l;
}

// ---------------- transpose + split: in[K,N] fp32 -> out[N,ldo] bf16 hi/lo --
__global__ void wtrans_k(const float* __restrict__ in,
                         bf16* __restrict__ oh, bf16* __restrict__ ol,
                         int K, int N, int ldo)
{
    __shared__ float t[32][33];
    long zoffi = (long)blockIdx.z*K*N;
    long zoffo = (long)blockIdx.z*N*ldo;
    int n0 = blockIdx.x*32, k0 = blockIdx.y*32;
    int tx = threadIdx.x, ty = threadIdx.y;
    #pragma unroll
    for (int i = ty; i < 32; i += 8) {
        int k = k0 + i, n = n0 + tx;
        t[i][tx] = (k < K && n < N) ? in[zoffi + (long)k*N + n] : 0.f;
    }
    __syncthreads();
    #pragma unroll
    for (int i = ty; i < 32; i += 8) {
        int n = n0 + i, k = k0 + tx;
        if (n < N && k < ldo) {
            bf16 h, l; split_bf16(t[tx][i], h, l);
            oh[zoffo + (long)n*ldo + k] = h;
            ol[zoffo + (long)n*ldo + k] = l;
        }
    }
}

// ---------------- v transpose + split --------------------------------------
__global__ void ktrans_k(const float* __restrict__ v,
                         bf16* __restrict__ oh, bf16* __restrict__ ol)
{
    long idx = (long)blockIdx.x*blockDim.x + threadIdx.x;
    long total = (long)Bt*NH*HD*S;
    if (idx >= total) return;
    int j = idx & 255; long r = idx >> 8;
    int d = r & 63; r >>= 6;
    int h = r & 7; int b = (int)(r >> 3);
    float x = v[((long)(b*S + j))*D + h*HD + d];
    bf16 hh, ll; split_bf16(x, hh, ll);
    oh[idx] = hh; ol[idx] = ll;
}

// ---------------- tcgen05 bf16 3-term GEMM ---------------------------------
// C[M,N] = (Ah+Al)[M,K] @ (Bh+Bl)[N,K]^T  using hh + hl + lh products.
// epi: 0 alpha  1 +bias  2 +bias+pos  3 +bias+residual  4 gelu(+bias)  5 gate*(+bias)
__global__ void __launch_bounds__(256, 1) tgemm_k(
    const bf16* __restrict__ Ah, const bf16* __restrict__ Al,
    const bf16* __restrict__ Bh, const bf16* __restrict__ Bl,
    float* __restrict__ C, bf16* __restrict__ Oh, bf16* __restrict__ Ol,
    int M, int N, int K, int lda, int ldb, int ldc,
    long sAo, long sAi, long sBo, long sBi, long sCo, long sCi, int zdiv,
    float alpha, const float* __restrict__ bias, long sBias,
    const float* __restrict__ extra, const int* __restrict__ gatherIdx,
    const float* __restrict__ gates, const int* __restrict__ eoff,
    const int* __restrict__ ecnt, int epi)
{
    extern __shared__ char dynsm[];

    int z = blockIdx.z;
    int zo = z / zdiv, zi = z - zo*zdiv;
    const bf16* Abh = Ah + zo*sAo + zi*sAi;
    const bf16* Abl = Al + zo*sAo + zi*sAi;
    const bf16* Bbh = Bh + zo*sBo + zi*sBi;
    const bf16* Bbl = Bl + zo*sBo + zi*sBi;
    int base = 0, Mloc = M;
    if (eoff) { base = eoff[z]; Mloc = (ecnt[z] + GBM - 1) & ~(GBM - 1); }
    int tm = blockIdx.x*GBM;
    if (tm >= Mloc) return;
    int tn = blockIdx.y*GBN;
    const float* biasb = bias ? (bias + (long)z*sBias) : nullptr;

    int tid = threadIdx.x;
    int wid = tid >> 5;

#if defined(__CUDA_ARCH__) && defined(__CUDA_ARCH_FEAT_SM103_ALL)
    __shared__ uint32_t s_tmem;
    __shared__ __align__(8) unsigned long long s_mbar[2];

    char* tb = (char*)(((uintptr_t)dynsm + 1023) & ~(uintptr_t)1023);
    uint32_t tb_u = smem_to_u32(tb);
    uint32_t mbar_u = smem_to_u32(&s_mbar[0]);

    if (tid == 0) { MBARRIER_INIT(mbar_u, 1); MBARRIER_INIT(mbar_u + 8, 1); }
    if (wid == 0) TCGEN05_ALLOC(smem_to_u32(&s_tmem), 128);
    __syncthreads();
    uint32_t tmem = s_tmem;

    const int NC = K / GBK;
    int ph0 = 0, ph1 = 0;

    for (int c = 0; c < NC; c++) {
        int buf = c & 1;
        if (c >= 2) {
            if (buf == 0) { MBARRIER_WAIT_PARITY(mbar_u,     ph0); ph0 ^= 1; }
            else          { MBARRIER_WAIT_PARITY(mbar_u + 8, ph1); ph1 ^= 1; }
        }
        int k0 = c*GBK;
        uint32_t bu = tb_u + buf*4*GTILE;
        #pragma unroll
        for (int i = 0; i < 4; i++) {
            int id = tid + i*256;           // 0..1023 segs of 16B
            int r = id >> 3, sg = id & 7;
            uint32_t boff = (uint32_t)(r*128 + sg*16);
            uint32_t sw = boff ^ ((boff >> 3) & 0x70);
            long arow = gatherIdx ? (long)gatherIdx[base + tm + r]
                                  : (long)(base + tm + r);
            long aoff = arow*lda + k0 + sg*8;
            CP_ASYNC16(bu + sw,           Abh + aoff);
            CP_ASYNC16(bu + GTILE + sw,   Abl + aoff);
            int gn = tn + r;
            if (gn < N) {
                long boff2 = (long)gn*ldb + k0 + sg*8;
                CP_ASYNC16(bu + 2*GTILE + sw, Bbh + boff2);
                CP_ASYNC16(bu + 3*GTILE + sw, Bbl + boff2);
            }
        }
        CP_COMMIT();
        CP_WAIT0();
        asm volatile("fence.proxy.async.shared::cta;" ::: "memory");
        __syncthreads();
        if (wid == 0) {
            if (elect_one_pred()) {
                uint64_t dAh = MAKE_SMEM_DESC(bu);
                uint64_t dAl = MAKE_SMEM_DESC(bu + GTILE);
                uint64_t dBh = MAKE_SMEM_DESC(bu + 2*GTILE);
                uint64_t dBl = MAKE_SMEM_DESC(bu + 3*GTILE);
                #pragma unroll
                for (int ks = 0; ks < 4; ks++)
                    TCGEN05_MMA_BF16_SS(tmem, dAh + ks*2, dBh + ks*2,
                                        (c > 0) || (ks > 0));
                #pragma unroll
                for (int ks = 0; ks < 4; ks++)
                    TCGEN05_MMA_BF16_SS(tmem, dAh + ks*2, dBl + ks*2, 1);
                #pragma unroll
                for (int ks = 0; ks < 4; ks++)
                    TCGEN05_MMA_BF16_SS(tmem, dAl + ks*2, dBh + ks*2, 1);
                TCGEN05_COMMIT(mbar_u + buf*8);
            }
        }
    }
    {
        int lb = (NC - 1) & 1;
        if (lb == 0) MBARRIER_WAIT_PARITY(mbar_u,     ph0);
        else         MBARRIER_WAIT_PARITY(mbar_u + 8, ph1);
    }
    TCGEN05_FENCE_AFTER();

    // ---- epilogue phase 1: TMEM -> SMEM with rotation swizzle --------------
    float* eb = (float*)tb;   // reuse staging buffer 0 (64KB), all MMAs done
    if (tid < 128) {
        #pragma unroll 1
        for (int g = 0; g < 4; g++) {
            uint32_t dr[32];
            TCGEN05_LD_32X32B_X32(dr, tmem + g*32);
            TCGEN05_WAIT_LD();
            #pragma unroll
            for (int j4 = 0; j4 < 8; j4++) {
                int grp = g*8 + j4;
                int rg = (grp + tid) & 31;
                float4 f4;
                f4.x = __uint_as_float(dr[j4*4+0]);
                f4.y = __uint_as_float(dr[j4*4+1]);
                f4.z = __uint_as_float(dr[j4*4+2]);
                f4.w = __uint_as_float(dr[j4*4+3]);
                *(float4*)(eb + (long)tid*128 + rg*4) = f4;
            }
        }
        TCGEN05_FENCE_BEFORE();
    }
    __syncthreads();
    // ---- epilogue phase 2: coalesced writes with fused epilogue -----------
    float* Cb = C ? (C + zo*sCo + zi*sCi) : nullptr;
    bf16* Ohb = Oh ? (Oh + zo*sCo + zi*sCi) : nullptr;
    bf16* Olb = Ol ? (Ol + zo*sCo + zi*sCi) : nullptr;
    #pragma unroll 1
    for (int i = 0; i < 16; i++) {
        int s2 = tid + i*256;
        int row = s2 >> 5, grp = s2 & 31;
        int colb = tn + grp*4;
        if (colb >= N) continue;
        int grow = tm + row;
        float4 f4 = *(float4*)(eb + (long)row*128 + ((grp + row) & 31)*4);
        float v[4] = {f4.x, f4.y, f4.z, f4.w};
        float gate = (epi == 5) ? gates[base + grow] : 1.f;
        #pragma unroll
        for (int jj = 0; jj < 4; jj++) {
            float t = v[jj]*alpha;
            int col = colb + jj;
            if (epi >= 1) t += biasb[col];
            if (epi == 2) t += extra[(long)(grow & (S-1))*ldc + col];
            else if (epi == 3) t += extra[(long)grow*ldc + col];
            else if (epi == 4) t = 0.5f*t*(1.0f + erff(t*0.70710678118654752f));
            else if (epi == 5) t *= gate;
            v[jj] = t;
        }
        long cidx = (long)(base + grow)*ldc + colb;
        if (Cb) *(float4*)(Cb + cidx) = make_float4(v[0], v[1], v[2], v[3]);
        if (Ohb) {
            bf16 h0, l0, h1, l1, h2, l2, h3, l3;
            split_bf16(v[0], h0, l0); split_bf16(v[1], h1, l1);
            split_bf16(v[2], h2, l2); split_bf16(v[3], h3, l3);
            uint2 ph, pl;
            ph.x = (uint32_t)__bfloat16_as_ushort(h0) | ((uint32_t)__bfloat16_as_ushort(h1) << 16);
            ph.y = (uint32_t)__bfloat16_as_ushort(h2) | ((uint32_t)__bfloat16_as_ushort(h3) << 16);
            pl.x = (uint32_t)__bfloat16_as_ushort(l0) | ((uint32_t)__bfloat16_as_ushort(l1) << 16);
            pl.y = (uint32_t)__bfloat16_as_ushort(l2) | ((uint32_t)__bfloat16_as_ushort(l3) << 16);
            *(uint2*)(Ohb + cidx) = ph;
            *(uint2*)(Olb + cidx) = pl;
        }
    }
    __syncthreads();
    if (wid == 0) {
        TCGEN05_RELINQ();
        TCGEN05_DEALLOC(tmem, 128);
    }
#else
    // generic fallback (compute_103 PTX stage only; never runs on sm_103a)
    (void)wid; (void)dynsm;
    float* Cb = C ? (C + zo*sCo + zi*sCi) : nullptr;
    bf16* Ohb = Oh ? (Oh + zo*sCo + zi*sCi) : nullptr;
    bf16* Olb = Ol ? (Ol + zo*sCo + zi*sCi) : nullptr;
    for (int rc = tid; rc < GBM*GBN; rc += 256) {
        int r = rc >> 7, c0 = rc & 127;
        int row = tm + r;
        int col = tn + c0;
        if (col >= N) continue;
        long arow = gatherIdx ? (long)gatherIdx[base + row] : (long)(base + row);
        float acc = 0.f;
        for (int k = 0; k < K; k++) {
            float a = __bfloat162float(Abh[arow*lda + k]) + __bfloat162float(Abl[arow*lda + k]);
            float b = __bfloat162float(Bbh[(long)col*ldb + k]) + __bfloat162float(Bbl[(long)col*ldb + k]);
            acc = fmaf(a, b, acc);
        }
        float t = acc*alpha;
        if (epi >= 1) t += biasb[col];
        if (epi == 2) t += extra[(long)(row & (S-1))*ldc + col];
        else if (epi == 3) t += extra[(long)row*ldc + col];
        else if (epi == 4) t = 0.5f*t*(1.0f + erff(t*0.70710678118654752f));
        else if (epi == 5) t *= gates[base + row];
        long cidx = (long)(base + row)*ldc + col;
        if (Cb) Cb[cidx] = t;
        if (Ohb) { bf16 h, l; split_bf16(t, h, l); Ohb[cidx] = h; Olb[cidx] = l; }
    }
#endif
}

// ---------------- small FFMA GEMM for the cls head (M=32) ------------------
#define OBM 64
#define OBN 64
#define OBK 16
__global__ void gemm_k(const float* __restrict__ A, const float* __restrict__ B,
                       float* __restrict__ C, int M, int N, int K,
                       int lda, int ldb, int ldc,
                       const float* __restrict__ bias)
{
    __shared__ float As[OBK][OBM];
    __shared__ float Bs[OBK][OBN+4];
    int tm = blockIdx.x*OBM;
    int tn = blockIdx.y*OBN;
    int tid = threadIdx.x;
    int tx = tid & 15, ty = tid >> 4;
    float acc[4][4] = {};
    for (int k0 = 0; k0 < K; k0 += OBK) {
        #pragma unroll
        for (int t = 0; t < 4; t++) {
            int id = tid + t*256;
            int r = id >> 4, c = id & 15;
            int gr = tm + r;
            float v = 0.f;
            if (gr < M && (k0 + c) < K) v = A[(long)gr*lda + k0 + c];
            As[c][r] = v;
        }
        #pragma unroll
        for (int t = 0; t < 4; t++) {
            int id = tid + t*256;
            int r = id >> 6, c = id & 63;
            float v = 0.f;
            if ((k0 + r) < K && (tn + c) < N) v = B[(long)(k0 + r)*ldb + tn + c];
            Bs[r][c] = v;
        }
        __syncthreads();
        #pragma unroll
        for (int kk = 0; kk < OBK; kk++) {
            float av[4], bv[4];
            #pragma unroll
            for (int i = 0; i < 4; i++) av[i] = As[kk][ty*4 + i];
            #pragma unroll
            for (int j = 0; j < 4; j++) bv[j] = Bs[kk][tx*4 + j];
            #pragma unroll
            for (int i = 0; i < 4; i++)
                #pragma unroll
                for (int j = 0; j < 4; j++)
                    acc[i][j] = fmaf(av[i], bv[j], acc[i][j]);
        }
        __syncthreads();
    }
    #pragma unroll
    for (int i = 0; i < 4; i++) {
        int row = tm + ty*4 + i;
        if (row >= M) continue;
        #pragma unroll
        for (int j = 0; j < 4; j++) {
            int col = tn + tx*4 + j;
            if (col >= N) continue;
            C[(long)row*ldc + col] = acc[i][j] + bias[col];
        }
    }
}

// ---------------- layernorm: fp32 out + split bf16 out ---------------------
__global__ void ln_k(const float* __restrict__ x, const float* __restrict__ g,
                     const float* __restrict__ b, float* __restrict__ y,
                     bf16* __restrict__ yh, bf16* __restrict__ yl)
{
    int row  = (blockIdx.x*blockDim.x + threadIdx.x) >> 5;
    int lane = threadIdx.x & 31;
    if (row >= T) return;
    const float* xr = x + (long)row*D;
    float v[16]; float s = 0.f;
    #pragma unroll
    for (int i = 0; i < 16; i++) { v[i] = xr[lane + 32*i]; s += v[i]; }
    #pragma unroll
    for (int o = 16; o > 0; o >>= 1) s += __shfl_xor_sync(~0u, s, o);
    float mean = s*(1.f/D);
    float vs = 0.f;
    #pragma unroll
    for (int i = 0; i < 16; i++) { float d = v[i]-mean; vs += d*d; }
    #pragma unroll
    for (int o = 16; o > 0; o >>= 1) vs += __shfl_xor_sync(~0u, vs, o);
    float rstd = rsqrtf(vs*(1.f/D) + 1e-5f);
    float* yr = y + (long)row*D;
    bf16* yhr = yh + (long)row*D;
    bf16* ylr = yl + (long)row*D;
    #pragma unroll
    for (int i = 0; i < 16; i++) {
        int c = lane + 32*i;
        float o = (v[i]-mean)*rstd*g[c] + b[c];
        yr[c] = o;
        bf16 h, l; split_bf16(o, h, l);
        yhr[c] = h; ylr[c] = l;
    }
}

// ---------------- softmax (256): fp32 in-place + split out -----------------
__global__ void softmax_k(float* __restrict__ a, int rows,
                          bf16* __restrict__ oh, bf16* __restrict__ ol)
{
    int row  = (blockIdx.x*blockDim.x + threadIdx.x) >> 5;
    int lane = threadIdx.x & 31;
    if (row >= rows) return;
    float* r = a + (long)row*S;
    bf16* rh = oh + (long)row*S;
    bf16* rl = ol + (long)row*S;
    float v[8]; float m = -1e30f;
    #pragma unroll
    for (int i = 0; i < 8; i++) { v[i] = r[lane + 32*i]; m = fmaxf(m, v[i]); }
    #pragma unroll
    for (int o = 16; o > 0; o >>= 1) m = fmaxf(m, __shfl_xor_sync(~0u, m, o));
    float s = 0.f;
    #pragma unroll
    for (int i = 0; i < 8; i++) { v[i] = expf(v[i]-m); s += v[i]; }
    #pragma unroll
    for (int o = 16; o > 0; o >>= 1) s += __shfl_xor_sync(~0u, s, o);
    float inv = 1.f/s;
    #pragma unroll
    for (int i = 0; i < 8; i++) {
        int c = lane + 32*i;
        float p = v[i]*inv;
        r[c] = p;
        bf16 h, l; split_bf16(p, h, l);
        rh[c] = h; rl[c] = l;
    }
}

// ---------------- head-mean + re-softmax -> attn_w -------------------------
__global__ void attnw_k(const float* __restrict__ attn, float* __restrict__ out)
{
    int row  = (blockIdx.x*blockDim.x + threadIdx.x) >> 5;
    int lane = threadIdx.x & 31;
    if (row >= T) return;
    int b = row >> 8, i = row & 255;
    const float* base = attn + ((long)b*NH*S + i)*S;
    float v[8];
    #pragma unroll
    for (int t = 0; t < 8; t++) {
        int j = lane + 32*t; float s = 0.f;
        #pragma unroll
        for (int h = 0; h < NH; h++) s += base[(long)h*S*S + j];
        v[t] = s*0.125f;
    }
    float m = -1e30f;
    #pragma unroll
    for (int t = 0; t < 8; t++) m = fmaxf(m, v[t]);
    #pragma unroll
    for (int o = 16; o > 0; o >>= 1) m = fmaxf(m, __shfl_xor_sync(~0u, m, o));
    float s = 0.f;
    #pragma unroll
    for (int t = 0; t < 8; t++) { v[t] = expf(v[t]-m); s += v[t]; }
    #pragma unroll
    for (int o = 16; o > 0; o >>= 1) s += __shfl_xor_sync(~0u, s, o);
    float inv = 1.f/s;
    float* orow = out + (long)row*S;
    #pragma unroll
    for (int t = 0; t < 8; t++) orow[lane + 32*t] = v[t]*inv;
}

// ---------------- MoE routing ----------------------------------------------
__global__ void route_k(const float* __restrict__ xln, const float* __restrict__ rw,
                        const float* __restrict__ rb, float* __restrict__ probs,
                        int* __restrict__ topi, float* __restrict__ topv)
{
    int tok  = (blockIdx.x*blockDim.x + threadIdx.x) >> 5;
    int lane = threadIdx.x & 31;
    if (tok >= T) return;
    const float* xr = xln + (long)tok*D;
    float acc[E] = {};
    for (int d = lane; d < D; d += 32) {
        float xv = xr[d];
        #pragma unroll
        for (int e = 0; e < E; e++) acc[e] = fmaf(xv, rw[d*E + e], acc[e]);
    }
    #pragma unroll
    for (int e = 0; e < E; e++)
        #pragma unroll
        for (int o = 16; o > 0; o >>= 1) acc[e] += __shfl_xor_sync(~0u, acc[e], o);
    if (lane == 0) {
        float mx = -1e30f;
        #pragma unroll
        for (int e = 0; e < E; e++) { acc[e] += rb[e]; mx = fmaxf(mx, acc[e]); }
        float s = 0.f, p[E];
        #pragma unroll
        for (int e = 0; e < E; e++) { p[e] = expf(acc[e]-mx); s += p[e]; }
        float inv = 1.f/s;
        int i0 = 0; float v0 = -1.f;
        #pragma unroll
        for (int e = 0; e < E; e++) { p[e] *= inv; probs[(long)tok*E + e] = p[e];
                                      if (p[e] > v0) { v0 = p[e]; i0 = e; } }
        int i1 = 0; float v1 = -1.f;
        #pragma unroll
        for (int e = 0; e < E; e++) { if (e != i0 && p[e] > v1) { v1 = p[e]; i1 = e; } }
        topi[tok*2] = i0;  topv[tok*2] = v0;
        topi[tok*2+1] = i1; topv[tok*2+1] = v1;
    }
}

// ---------------- bucket build ---------------------------------------------
__global__ void bucket_k(const int* __restrict__ topi, const float* __restrict__ topv,
                         int* __restrict__ btok, float* __restrict__ bgate,
                         int* __restrict__ slot, int* __restrict__ eoff,
                         int* __restrict__ ecnt, int* __restrict__ ecnt_raw)
{
    __shared__ int cnt[E], off[E], cur[E];
    int tid = threadIdx.x;
    if (tid < E) cnt[tid] = 0;
    __syncthreads();
    for (int t = tid; t < T; t += 256) {
        atomicAdd(&cnt[topi[t*2]], 1);
        atomicAdd(&cnt[topi[t*2+1]], 1);
    }
    __syncthreads();
    if (tid == 0) {
        int o = 0;
        for (int e = 0; e < E; e++) { off[e] = o; o += (cnt[e] + GBM - 1) & ~(GBM - 1); }
    }
    __syncthreads();
    if (tid < E) {
        cur[tid] = off[tid];
        eoff[tid] = off[tid];
        ecnt[tid] = cnt[tid];
        ecnt_raw[tid] = cnt[tid];
    }
    __syncthreads();
    for (int t = tid; t < T; t += 256) {
        #pragma unroll
        for (int k = 0; k < 2; k++) {
            int e = topi[t*2 + k];
            int pos = atomicAdd(&cur[e], 1);
            btok[pos] = t;
            bgate[pos] = topv[t*2 + k];
            slot[t*2 + k] = pos;
        }
    }
    __syncthreads();
    for (int e = 0; e < E; e++) {
        int start = off[e] + cnt[e];
        int end   = off[e] + ((cnt[e] + GBM - 1) & ~(GBM - 1));
        for (int p = start + tid; p < end; p += 256) { btok[p] = 0; bgate[p] = 0.f; }
    }
}

// ---------------- combine 2 slot contributions -----------------------------
__global__ void combine_k(const int* __restrict__ slot, const float* __restrict__ contrib,
                          float* __restrict__ out)
{
    long idx = (long)blockIdx.x*blockDim.x + threadIdx.x;
    if (idx >= (long)T*D) return;
    int t = (int)(idx >> 9), d = (int)(idx & 511);
    int s0 = slot[t*2], s1 = slot[t*2+1];
    out[idx] = contrib[(long)s0*D + d] + contrib[(long)s1*D + d];
}

// ---------------- aux loss -------------------------------------------------
__global__ void loss_k(const float* __restrict__ probs, const int* __restrict__ ecnt_raw,
                       float* __restrict__ out, int accum)
{
    __shared__ float red[256*E];
    int tid = threadIdx.x;
    float acc[E] = {};
    for (int t = tid; t < T; t += 256)
        #pragma unroll
        for (int e = 0; e < E; e++) acc[e] += probs[(long)t*E + e];
    #pragma unroll
    for (int e = 0; e < E; e++) red[tid*E + e] = acc[e];
    __syncthreads();
    for (int s = 128; s > 0; s >>= 1) {
        if (tid < s)
            #pragma unroll
            for (int e = 0; e < E; e++) red[tid*E + e] += red[(tid + s)*E + e];
        __syncthreads();
    }
    if (tid == 0) {
        float l = 0.f;
        for (int e = 0; e < E; e++) {
            float imp  = red[e]*(1.f/T);
            float frac = (float)ecnt_raw[e]*(1.f/T);
            l += frac*imp;
        }
        l *= (float)E;
        if (accum) out[0] += l; else out[0] = l;
    }
}

// ---------------- fv mean over S -------------------------------------------
__global__ void fv_k(const float* __restrict__ o2, float* __restrict__ fv)
{
    int b = blockIdx.x, d = threadIdx.x;
    float s = 0.f;
    for (int i = 0; i < S; i++) s += o2[((long)b*S + i)*D + d];
    fv[b*D + d] = s*(1.f/S);
}

__global__ void writeloss_k(const float* __restrict__ loss, float* __restrict__ out)
{
    out[0] = loss[0];
}

// ---------------- host -----------------------------------------------------
#define SYM(p, s) cudaGetSymbolAddress((void**)&p, s)

extern "C" void kernel_launch(void* const* d_in, const int* in_sizes, int n_in,
                              void* d_out, int out_size)
{
    const float* x    = (const float*)d_in[0];
    const float* pe_w = (const float*)d_in[1];
    const float* pe_b = (const float*)d_in[2];
    const float* pos  = (const float*)d_in[3];
    const float* ln1g = (const float*)d_in[4];
    const float* ln1b = (const float*)d_in[5];
    const float* ln2g = (const float*)d_in[6];
    const float* ln2b = (const float*)d_in[7];
    const float* ln3g = (const float*)d_in[8];
    const float* ln3b = (const float*)d_in[9];
    const float* wq = (const float*)d_in[10]; const float* bq = (const float*)d_in[11];
    const float* wk = (const float*)d_in[12]; const float* bk = (const float*)d_in[13];
    const float* wv = (const float*)d_in[14]; const float* bv = (const float*)d_in[15];
    const float* wo = (const float*)d_in[16]; const float* bo = (const float*)d_in[17];
    const float* m1rw = (const float*)d_in[18]; const float* m1rb = (const float*)d_in[19];
    const float* m1w1 = (const float*)d_in[20]; const float* m1b1 = (const float*)d_in[21];
    const float* m1w2 = (const float*)d_in[22]; const float* m1b2 = (const float*)d_in[23];
    const float* m2rw = (const float*)d_in[24]; const float* m2rb = (const float*)d_in[25];
    const float* m2w1 = (const float*)d_in[26]; const float* m2b1 = (const float*)d_in[27];
    const float* m2w2 = (const float*)d_in[28]; const float* m2b2 = (const float*)d_in[29];
    const float* clsw = (const float*)d_in[30]; const float* clsb = (const float*)d_in[31];
    float* out = (float*)d_out;

    cudaFuncSetAttribute(tgemm_k, cudaFuncAttributeMaxDynamicSharedMemorySize, DYNSM);

    float *p_e, *p_ln, *p_v, *p_attn, *p_x2, *p_contrib, *p_o1, *p_o2;
    float *p_probs, *p_topv, *p_bgate, *p_loss;
    int *p_topi, *p_btok, *p_slot, *p_eoff, *p_ecnt, *p_ecnt_raw;
    bf16 *patH,*patL,*lnH,*lnL,*qH,*qL,*kH,*kL,*vTH,*vTL,*attnH,*attnL,*avH,*avL,*hbH,*hbL;
    bf16 *petH,*petL,*wqtH,*wqtL,*wktH,*wktL,*wvtH,*wvtL,*wotH,*wotL;
    bf16 *w1aH,*w1aL,*w2aH,*w2aL,*w1bH,*w1bL,*w2bH,*w2bL;
    SYM(p_e, g_e); SYM(p_ln, g_ln); SYM(p_v, g_v); SYM(p_attn, g_attn);
    SYM(p_x2, g_x2); SYM(p_contrib, g_contrib); SYM(p_o1, g_o1); SYM(p_o2, g_o2);
    SYM(p_probs, g_probs); SYM(p_topv, g_topv); SYM(p_bgate, g_bgate); SYM(p_loss, g_loss);
    SYM(p_topi, g_topi); SYM(p_btok, g_btok); SYM(p_slot, g_slot);
    SYM(p_eoff, g_eoff); SYM(p_ecnt, g_ecnt); SYM(p_ecnt_raw, g_ecnt_raw);
    SYM(patH, g_patH); SYM(patL, g_patL); SYM(lnH, g_lnH); SYM(lnL, g_lnL);
    SYM(qH, g_qH); SYM(qL, g_qL); SYM(kH, g_kH); SYM(kL, g_kL);
    SYM(vTH, g_vTH); SYM(vTL, g_vTL); SYM(attnH, g_attnH); SYM(attnL, g_attnL);
    SYM(avH, g_avH); SYM(avL, g_avL); SYM(hbH, g_hbufH); SYM(hbL, g_hbufL);
    SYM(petH, g_petH); SYM(petL, g_petL); SYM(wqtH, g_wqtH); SYM(wqtL, g_wqtL);
    SYM(wktH, g_wktH); SYM(wktL, g_wktL); SYM(wvtH, g_wvtH); SYM(wvtL, g_wvtL);
    SYM(wotH, g_wotH); SYM(wotL, g_wotL);
    SYM(w1aH, g_w1t1H); SYM(w1aL, g_w1t1L); SYM(w2aH, g_w2t1H); SYM(w2aL, g_w2t1L);
    SYM(w1bH, g_w1t2H); SYM(w1bL, g_w1t2L); SYM(w2bH, g_w2t2H); SYM(w2bL, g_w2t2L);

    dim3 tt(32, 8);
    long Z6 = 0;
    // [0] patchify (split, padded)
    { long tot = (long)T*PDK;
      patchify_k<<<(int)((tot + 255)/256), 256>>>(x, patH, patL); }
    // [1] pe_w transpose+split
    wtrans_k<<<dim3(16, 20, 1), tt>>>(pe_w, petH, petL, PD, D, PDK);
    // [2] embed GEMM -> e fp32
    tgemm_k<<<dim3(T/GBM, D/GBN, 1), 256, DYNSM>>>(patH, patL, petH, petL,
        p_e, nullptr, nullptr, T, D, PDK, PDK, PDK, D,
        Z6,Z6,Z6,Z6,Z6,Z6,1, 1.f, pe_b, 0, pos, nullptr, nullptr, nullptr, nullptr, 2);
    // [3] ln1 -> fp32 + split
    ln_k<<<T*32/256, 256>>>(p_e, ln1g, ln1b, p_ln, lnH, lnL);
    // [4] wq transpose
    wtrans_k<<<dim3(16, 16, 1), tt>>>(wq, wqtH, wqtL, D, D, D);
    // [5] q GEMM (split-only out)   <- ncu -s 5 profiles this
    tgemm_k<<<dim3(T/GBM, D/GBN, 1), 256, DYNSM>>>(lnH, lnL, wqtH, wqtL,
        nullptr, qH, qL, T, D, D, D, D, D,
        Z6,Z6,Z6,Z6,Z6,Z6,1, 1.f, bq, 0, nullptr, nullptr, nullptr, nullptr, nullptr, 1);
    wtrans_k<<<dim3(16, 16, 1), tt>>>(wk, wktH, wktL, D, D, D);
    tgemm_k<<<dim3(T/GBM, D/GBN, 1), 256, DYNSM>>>(lnH, lnL, wktH, wktL,
        nullptr, kH, kL, T, D, D, D, D, D,
        Z6,Z6,Z6,Z6,Z6,Z6,1, 1.f, bk, 0, nullptr, nullptr, nullptr, nullptr, nullptr, 1);
    wtrans_k<<<dim3(16, 16, 1), tt>>>(wv, wvtH, wvtL, D, D, D);
    tgemm_k<<<dim3(T/GBM, D/GBN, 1), 256, DYNSM>>>(lnH, lnL, wvtH, wvtL,
        p_v, nullptr, nullptr, T, D, D, D, D, D,
        Z6,Z6,Z6,Z6,Z6,Z6,1, 1.f, bv, 0, nullptr, nullptr, nullptr, nullptr, nullptr, 1);
    // vT transpose+split
    { long tot = (long)Bt*NH*HD*S;
      ktrans_k<<<(int)((tot + 255)/256), 256>>>(p_v, vTH, vTL); }
    // scores = q @ k^T / 8
    tgemm_k<<<dim3(2, 2, Bt*NH), 256, DYNSM>>>(qH, qL, kH, kL,
        p_attn, nullptr, nullptr, S, S, HD, D, D, S,
        (long)S*D, (long)HD, (long)S*D, (long)HD, (long)NH*S*S, (long)S*S, NH,
        0.125f, nullptr, 0, nullptr, nullptr, nullptr, nullptr, nullptr, 0);
    // softmax (fp32 in place + split)
    softmax_k<<<Bt*NH*S*32/256, 256>>>(p_attn, Bt*NH*S, attnH, attnL);
    attnw_k<<<T*32/256, 256>>>(p_attn, out + 32769);
    // av = attn @ v (split-only out)
    tgemm_k<<<dim3(2, 1, Bt*NH), 256, DYNSM>>>(attnH, attnL, vTH, vTL,
        nullptr, avH, avL, S, HD, S, S, S, D,
        (long)NH*S*S, (long)S*S, (long)NH*HD*S, (long)HD*S, (long)S*D, (long)HD, NH,
        1.f, nullptr, 0, nullptr, nullptr, nullptr, nullptr, nullptr, 0);
    // out proj + residual
    wtrans_k<<<dim3(16, 16, 1), tt>>>(wo, wotH, wotL, D, D, D);
    tgemm_k<<<dim3(T/GBM, D/GBN, 1), 256, DYNSM>>>(avH, avL, wotH, wotL,
        p_x2, nullptr, nullptr, T, D, D, D, D, D,
        Z6,Z6,Z6,Z6,Z6,Z6,1, 1.f, bo, 0, p_e, nullptr, nullptr, nullptr, nullptr, 3);

    // ----- MoE layer 1 -----
    ln_k<<<T*32/256, 256>>>(p_x2, ln2g, ln2b, p_ln, lnH, lnL);
    route_k<<<T*32/256, 256>>>(p_ln, m1rw, m1rb, p_probs, p_topi, p_topv);
    bucket_k<<<1, 256>>>(p_topi, p_topv, p_btok, p_bgate, p_slot, p_eoff, p_ecnt, p_ecnt_raw);
    wtrans_k<<<dim3(64, 16, E), tt>>>(m1w1, w1aH, w1aL, D, HID, D);
    tgemm_k<<<dim3(64, HID/GBN, E), 256, DYNSM>>>(lnH, lnL, w1aH, w1aL,
        nullptr, hbH, hbL, 0, HID, D, D, D, HID,
        Z6,Z6,(long)HID*D,Z6,Z6,Z6,1, 1.f, m1b1, HID, nullptr, p_btok, nullptr,
        p_eoff, p_ecnt, 4);
    wtrans_k<<<dim3(16, 64, E), tt>>>(m1w2, w2aH, w2aL, HID, D, HID);
    tgemm_k<<<dim3(64, D/GBN, E), 256, DYNSM>>>(hbH, hbL, w2aH, w2aL,
        p_contrib, nullptr, nullptr, 0, D, HID, HID, HID, D,
        Z6,Z6,(long)D*HID,Z6,Z6,Z6,1, 1.f, m1b2, D, nullptr, nullptr, p_bgate,
        p_eoff, p_ecnt, 5);
    combine_k<<<T*D/256, 256>>>(p_slot, p_contrib, p_o1);
    loss_k<<<1, 256>>>(p_probs, p_ecnt_raw, p_loss, 0);

    // ----- MoE layer 2 -----
    ln_k<<<T*32/256, 256>>>(p_o1, ln3g, ln3b, p_ln, lnH, lnL);
    route_k<<<T*32/256, 256>>>(p_ln, m2rw, m2rb, p_probs, p_topi, p_topv);
    bucket_k<<<1, 256>>>(p_topi, p_topv, p_btok, p_bgate, p_slot, p_eoff, p_ecnt, p_ecnt_raw);
    wtrans_k<<<dim3(64, 16, E), tt>>>(m2w1, w1bH, w1bL, D, HID, D);
    tgemm_k<<<dim3(64, HID/GBN, E), 256, DYNSM>>>(lnH, lnL, w1bH, w1bL,
        nullptr, hbH, hbL, 0, HID, D, D, D, HID,
        Z6,Z6,(long)HID*D,Z6,Z6,Z6,1, 1.f, m2b1, HID, nullptr, p_btok, nullptr,
        p_eoff, p_ecnt, 4);
    wtrans_k<<<dim3(16, 64, E), tt>>>(m2w2, w2bH, w2bL, HID, D, HID);
    tgemm_k<<<dim3(64, D/GBN, E), 256, DYNSM>>>(hbH, hbL, w2bH, w2bL,
        p_contrib, nullptr, nullptr, 0, D, HID, HID, HID, D,
        Z6,Z6,(long)D*HID,Z6,Z6,Z6,1, 1.f, m2b2, D, nullptr, nullptr, p_bgate,
        p_eoff, p_ecnt, 5);
    combine_k<<<T*D/256, 256>>>(p_slot, p_contrib, p_o2);
    loss_k<<<1, 256>>>(p_probs, p_ecnt_raw, p_loss, 1);

    // fv, logits, loss
    fv_k<<<Bt, D>>>(p_o2, out + 16384);
    gemm_k<<<dim3(1, D/OBN, 1), 256>>>(out + 16384, clsw, out, Bt, D, D, D, D, D, clsb);
    writeloss_k<<<1, 1>>>(p_loss, out + 32768);
}

// round 9
// speedup vs baseline: 5.4908x; 1.1692x over previous
#include <cuda_runtime.h>
#include <cuda_bf16.h>
#include <cstdint>
#include <math.h>

#define Bt   32
#define S    256
#define T    8192      // Bt*S
#define D    512
#define PD   588
#define PDK  640       // PD padded to multiple of 64
#define NH   8
#define HD   64
#define E    8
#define HID  2048
#define GBM  256
#define GBN  256
#define GBK  32
#define TTILE 16384    // one term tile: 256 rows * 64 bytes
#define NSLOT 18432    // 16384 + 8*256 padding
#define DYNSM 132096   // 2 bufs * 4 term-tiles * 16KB + align slack

typedef __nv_bfloat16 bf16;

// ---------------------------------------------------------------------------
// PTX helpers
// ---------------------------------------------------------------------------
__device__ __forceinline__ uint32_t elect_one_pred() {
    uint32_t pred;
    asm volatile(
        "{\n\t.reg .pred p;\n\telect.sync _|p, 0xFFFFFFFF;\n\t"
        "selp.b32 %0, 1, 0, p;\n\t}" : "=r"(pred));
    return pred;
}
__device__ __forceinline__ uint32_t smem_to_u32(const void* p) {
    uint32_t a;
    asm("{ .reg .u64 t; cvta.to.shared.u64 t, %1; cvt.u32.u64 %0, t; }"
        : "=r"(a) : "l"(p));
    return a;
}

// SW64: atom = 8 rows x 64B. layout=4, SBO=32 (8 rows*64B=512B), LBO=1 (16B)
static constexpr uint64_t SMEM_DESC_BASE_SW64 =
    (uint64_t(4)  << 61) | (uint64_t(1) << 46) | (uint64_t(32) << 32) | (uint64_t(1) << 16);
#define MAKE_SMEM_DESC64(base_addr) \
    (SMEM_DESC_BASE_SW64 | ((uint64_t)((base_addr) >> 4) & 0x3FFF))
#define SW64(off) ((off) ^ (((off) >> 3) & 0x30))

#define TCGEN05_ALLOC(smem_result_addr, nCols) \
    asm volatile("tcgen05.alloc.cta_group::1.sync.aligned.shared::cta.b32 [%0], %1;" \
        :: "r"((uint32_t)(smem_result_addr)), "r"((uint32_t)(nCols)) : "memory")
#define TCGEN05_DEALLOC(tmem_addr, nCols) \
    asm volatile("tcgen05.dealloc.cta_group::1.sync.aligned.b32 %0, %1;" \
        :: "r"(tmem_addr), "r"((uint32_t)(nCols)))
#define TCGEN05_RELINQ() \
    asm volatile("tcgen05.relinquish_alloc_permit.cta_group::1.sync.aligned;")
#define TCGEN05_COMMIT(mbar_smem_addr) \
    asm volatile("tcgen05.commit.cta_group::1.mbarrier::arrive::one.shared::cluster.b64 [%0];" \
        :: "r"((uint32_t)(mbar_smem_addr)) : "memory")
#define TCGEN05_FENCE_AFTER() \
    asm volatile("tcgen05.fence::after_thread_sync;" ::: "memory")
#define TCGEN05_FENCE_BEFORE() \
    asm volatile("tcgen05.fence::before_thread_sync;" ::: "memory")
#define TCGEN05_WAIT_LD() \
    asm volatile("tcgen05.wait::ld.sync.aligned;" ::: "memory")

#define TCGEN05_LD_32X32B_X32(r, tmem_addr) \
    asm volatile( \
        "tcgen05.ld.sync.aligned.32x32b.x32.b32 " \
        "{%0, %1, %2, %3, %4, %5, %6, %7, " \
        " %8, %9, %10, %11, %12, %13, %14, %15, " \
        " %16, %17, %18, %19, %20, %21, %22, %23, " \
        " %24, %25, %26, %27, %28, %29, %30, %31}, [%32];" \
        : "=r"((r)[0]),  "=r"((r)[1]),  "=r"((r)[2]),  "=r"((r)[3]), \
          "=r"((r)[4]),  "=r"((r)[5]),  "=r"((r)[6]),  "=r"((r)[7]), \
          "=r"((r)[8]),  "=r"((r)[9]),  "=r"((r)[10]), "=r"((r)[11]), \
          "=r"((r)[12]), "=r"((r)[13]), "=r"((r)[14]), "=r"((r)[15]), \
          "=r"((r)[16]), "=r"((r)[17]), "=r"((r)[18]), "=r"((r)[19]), \
          "=r"((r)[20]), "=r"((r)[21]), "=r"((r)[22]), "=r"((r)[23]), \
          "=r"((r)[24]), "=r"((r)[25]), "=r"((r)[26]), "=r"((r)[27]), \
          "=r"((r)[28]), "=r"((r)[29]), "=r"((r)[30]), "=r"((r)[31]) \
        : "r"(tmem_addr))

#define MBARRIER_INIT(mbar_smem_addr, count) \
    asm volatile("mbarrier.init.shared.b64 [%0], %1;" \
        :: "r"((uint32_t)(mbar_smem_addr)), "r"((uint32_t)(count)) : "memory")

#define MBARRIER_WAIT_PARITY(mbar_smem_addr, phase_parity) do { \
    uint32_t _mbar = (uint32_t)(mbar_smem_addr); \
    uint32_t _parity = (uint32_t)(phase_parity); \
    uint32_t _done; \
    asm volatile( \
        "{\n\t.reg .pred p;\n\t" \
        "mbarrier.try_wait.parity.acquire.cta.shared::cta.b64 p, [%1], %2;\n\t" \
        "selp.b32 %0, 1, 0, p;\n\t}" \
        : "=r"(_done) : "r"(_mbar), "r"(_parity) : "memory"); \
    if (!_done) { \
        asm volatile( \
            "{\n\t.reg .pred P1;\n\t" \
            "WAIT_LOOP_%=:\n\t" \
            "mbarrier.try_wait.parity.acquire.cta.shared::cta.b64 P1, [%0], %1, 0x989680;\n\t" \
            "@P1 bra.uni WAIT_DONE_%=;\n\t" \
            "bra.uni WAIT_LOOP_%=;\n\t" \
            "WAIT_DONE_%=:\n\t}" \
            :: "r"(_mbar), "r"(_parity) : "memory"); \
    } \
} while(0)

#define CP_ASYNC16(dst_u32, src_ptr) \
    asm volatile("cp.async.cg.shared.global [%0], [%1], 16;" \
        :: "r"((uint32_t)(dst_u32)), "l"(src_ptr) : "memory")
#define CP_COMMIT() asm volatile("cp.async.commit_group;" ::: "memory")
#define CP_WAIT0()  asm volatile("cp.async.wait_group 0;" ::: "memory")

// idesc kind::f16 (bf16): F32(1)<<4 | BF16(1)<<7 | BF16(1)<<10 | (N/8)<<17 | (M/16)<<24
#define IDESC_BASE 0x08000490u

#define TCGEN05_MMA_BF16_SS(d_tmem, a_desc, b_desc, idesc, enable) do { \
    uint32_t _en = (uint32_t)(enable); \
    asm volatile( \
        "{\n\t.reg .pred p;\n\tsetp.ne.u32 p, %5, 0;\n\t" \
        "tcgen05.mma.cta_group::1.kind::f16 [%0], %1, %2, %3, {%4, %4, %4, %4}, p;\n\t}" \
        :: "r"(d_tmem), "l"(a_desc), "l"(b_desc), "r"(idesc), "r"(0u), "r"(_en) \
        : "memory"); \
} while(0)

__device__ __forceinline__ void split_bf16(float x, bf16& h, bf16& l) {
    h = __float2bfloat16(x);
    l = __float2bfloat16(x - __bfloat162float(h));
}

// ---------------- scratch ---------------------------------------------------
__device__ float g_e[(long)T*D];
__device__ float g_ln[(long)T*D];
__device__ float g_v[(long)T*D];
__device__ float g_attn[(long)Bt*NH*S*S];
__device__ float g_x2[(long)T*D];
__device__ float g_contrib[(long)NSLOT*D];
__device__ float g_o1[(long)T*D];
__device__ float g_o2[(long)T*D];
__device__ float g_probs[(long)T*E];
__device__ int   g_topi[T*2];
__device__ float g_topv[T*2];
__device__ int   g_btok[NSLOT];
__device__ float g_bgate[NSLOT];
__device__ int   g_slot[T*2];
__device__ int   g_eoff[E];
__device__ int   g_ecnt[E];
__device__ int   g_ecnt_raw[E];
__device__ float g_loss[1];
// split-bf16 activations
__device__ bf16 g_patH[(long)T*PDK],  g_patL[(long)T*PDK];
__device__ bf16 g_lnH[(long)T*D],     g_lnL[(long)T*D];
__device__ bf16 g_qH[(long)T*D],      g_qL[(long)T*D];
__device__ bf16 g_kH[(long)T*D],      g_kL[(long)T*D];
__device__ bf16 g_vTH[(long)Bt*NH*HD*S], g_vTL[(long)Bt*NH*HD*S];
__device__ bf16 g_attnH[(long)Bt*NH*S*S], g_attnL[(long)Bt*NH*S*S];
__device__ bf16 g_avH[(long)T*D],     g_avL[(long)T*D];
__device__ bf16 g_hbufH[(long)NSLOT*HID], g_hbufL[(long)NSLOT*HID];
// split-bf16 transposed weights [N,K]
__device__ bf16 g_petH[(long)D*PDK],  g_petL[(long)D*PDK];
__device__ bf16 g_wqtH[(long)D*D],    g_wqtL[(long)D*D];
__device__ bf16 g_wktH[(long)D*D],    g_wktL[(long)D*D];
__device__ bf16 g_wvtH[(long)D*D],    g_wvtL[(long)D*D];
__device__ bf16 g_wotH[(long)D*D],    g_wotL[(long)D*D];
__device__ bf16 g_w1t1H[(long)E*HID*D], g_w1t1L[(long)E*HID*D];
__device__ bf16 g_w2t1H[(long)E*D*HID], g_w2t1L[(long)E*D*HID];
__device__ bf16 g_w1t2H[(long)E*HID*D], g_w1t2L[(long)E*HID*D];
__device__ bf16 g_w2t2H[(long)E*D*HID], g_w2t2L[(long)E*D*HID];

// ---------------- patchify (writes split directly, K padded) ----------------
__global__ void patchify_k(const float* __restrict__ x,
                           bf16* __restrict__ oh, bf16* __restrict__ ol)
{
    long idx = (long)blockIdx.x*blockDim.x + threadIdx.x;
    long total = (long)T*PDK;
    if (idx >= total) return;
    int i = idx % PDK;
    long r = idx / PDK;
    float v = 0.f;
    if (i < PD) {
        int s = r % S;
        int b = r / S;
        int c  = i % 3;
        int t  = i / 3;
        int p2 = t % 14;
        int p1 = t / 14;
        int hh = s >> 4, ww = s & 15;
        v = x[(((long)(b*3 + c)*224) + hh*14 + p1)*224 + ww*14 + p2];
    }
    bf16 h, l; split_bf16(v, h, l);
    oh[idx] = h; ol[idx] = l;
}

// ---------------- transpose + split: in[K,N] fp32 -> out[N,ldo] bf16 hi/lo --
__global__ void wtrans_k(const float* __restrict__ in,
                         bf16* __restrict__ oh, bf16* __restrict__ ol,
                         int K, int N, int ldo)
{
    __shared__ float t[32][33];
    long zoffi = (long)blockIdx.z*K*N;
    long zoffo = (long)blockIdx.z*N*ldo;
    int n0 = blockIdx.x*32, k0 = blockIdx.y*32;
    int tx = threadIdx.x, ty = threadIdx.y;
    #pragma unroll
    for (int i = ty; i < 32; i += 8) {
        int k = k0 + i, n = n0 + tx;
        t[i][tx] = (k < K && n < N) ? in[zoffi + (long)k*N + n] : 0.f;
    }
    __syncthreads();
    #pragma unroll
    for (int i = ty; i < 32; i += 8) {
        int n = n0 + i, k = k0 + tx;
        if (n < N && k < ldo) {
            bf16 h, l; split_bf16(t[tx][i], h, l);
            oh[zoffo + (long)n*ldo + k] = h;
            ol[zoffo + (long)n*ldo + k] = l;
        }
    }
}

// ---------------- v transpose + split --------------------------------------
__global__ void ktrans_k(const float* __restrict__ v,
                         bf16* __restrict__ oh, bf16* __restrict__ ol)
{
    long idx = (long)blockIdx.x*blockDim.x + threadIdx.x;
    long total = (long)Bt*NH*HD*S;
    if (idx >= total) return;
    int j = idx & 255; long r = idx >> 8;
    int d = r & 63; r >>= 6;
    int h = r & 7; int b = (int)(r >> 3);
    float x = v[((long)(b*S + j))*D + h*HD + d];
    bf16 hh, ll; split_bf16(x, hh, ll);
    oh[idx] = hh; ol[idx] = ll;
}

// ---------------- tcgen05 bf16 3-term GEMM, 256x256 tiles ------------------
// C[M,N] = (Ah+Al)[M,K] @ (Bh+Bl)[N,K]^T  using hh + hl + lh products.
// Tile: 256x256 per CTA (two M=128 MMA groups). K chunks of 32 (SW64 64B rows).
// epi: 0 alpha  1 +bias  2 +bias+pos  3 +bias+residual  4 gelu(+bias)  5 gate*(+bias)
__global__ void __launch_bounds__(256, 1) tgemm_k(
    const bf16* __restrict__ Ah, const bf16* __restrict__ Al,
    const bf16* __restrict__ Bh, const bf16* __restrict__ Bl,
    float* __restrict__ C, bf16* __restrict__ Oh, bf16* __restrict__ Ol,
    int M, int N, int K, int lda, int ldb, int ldc, uint32_t idesc,
    long sAo, long sAi, long sBo, long sBi, long sCo, long sCi, int zdiv,
    float alpha, const float* __restrict__ bias, long sBias,
    const float* __restrict__ extra, const int* __restrict__ gatherIdx,
    const float* __restrict__ gates, const int* __restrict__ eoff,
    const int* __restrict__ ecnt, int epi)
{
    extern __shared__ char dynsm[];

    int z = blockIdx.z;
    int zo = z / zdiv, zi = z - zo*zdiv;
    const bf16* Abh = Ah + zo*sAo + zi*sAi;
    const bf16* Abl = Al + zo*sAo + zi*sAi;
    const bf16* Bbh = Bh + zo*sBo + zi*sBi;
    const bf16* Bbl = Bl + zo*sBo + zi*sBi;
    int base = 0, Mloc = M;
    if (eoff) { base = eoff[z]; Mloc = (ecnt[z] + GBM - 1) & ~(GBM - 1); }
    int tm = blockIdx.x*GBM;
    if (tm >= Mloc) return;
    int tn = blockIdx.y*GBN;
    const float* biasb = bias ? (bias + (long)z*sBias) : nullptr;

    int tid = threadIdx.x;
    int wid = tid >> 5;

#if defined(__CUDA_ARCH__) && defined(__CUDA_ARCH_FEAT_SM103_ALL)
    __shared__ uint32_t s_tmem;
    __shared__ __align__(8) unsigned long long s_mbar[2];

    char* tb = (char*)(((uintptr_t)dynsm + 1023) & ~(uintptr_t)1023);
    uint32_t tb_u = smem_to_u32(tb);
    uint32_t mbar_u = smem_to_u32(&s_mbar[0]);

    if (tid == 0) { MBARRIER_INIT(mbar_u, 1); MBARRIER_INIT(mbar_u + 8, 1); }
    if (wid == 0) TCGEN05_ALLOC(smem_to_u32(&s_tmem), 512);
    __syncthreads();
    uint32_t tmem = s_tmem;

    const int NC = K / GBK;
    int ph0 = 0, ph1 = 0;

    for (int c = 0; c < NC; c++) {
        int buf = c & 1;
        if (c >= 2) {
            if (buf == 0) { MBARRIER_WAIT_PARITY(mbar_u,     ph0); ph0 ^= 1; }
            else          { MBARRIER_WAIT_PARITY(mbar_u + 8, ph1); ph1 ^= 1; }
        }
        int k0 = c*GBK;
        uint32_t bu = tb_u + buf*4*TTILE;
        // A: 2 terms * 256 rows * 4 segs(16B) = 2048 segs
        #pragma unroll
        for (int i = 0; i < 8; i++) {
            int id = tid + i*256;
            int term = id >> 10;
            int r = (id >> 2) & 255;
            int sg = id & 3;
            uint32_t off = (uint32_t)(r*64 + sg*16);
            uint32_t sw = SW64(off);
            long arow = gatherIdx ? (long)gatherIdx[base + tm + r]
                                  : (long)(base + tm + r);
            const bf16* src = (term ? Abl : Abh) + arow*lda + k0 + sg*8;
            CP_ASYNC16(bu + term*TTILE + sw, src);
        }
        // B: 2 terms * 256 rows * 4 segs
        #pragma unroll
        for (int i = 0; i < 8; i++) {
            int id = tid + i*256;
            int term = id >> 10;
            int r = (id >> 2) & 255;
            int sg = id & 3;
            int gn = tn + r;
            if (gn < N) {
                uint32_t off = (uint32_t)(r*64 + sg*16);
                uint32_t sw = SW64(off);
                const bf16* src = (term ? Bbl : Bbh) + (long)gn*ldb + k0 + sg*8;
                CP_ASYNC16(bu + (2 + term)*TTILE + sw, src);
            }
        }
        CP_COMMIT();
        CP_WAIT0();
        asm volatile("fence.proxy.async.shared::cta;" ::: "memory");
        __syncthreads();
        if (wid == 0) {
            if (elect_one_pred()) {
                uint64_t dBh = MAKE_SMEM_DESC64(bu + 2*TTILE);
                uint64_t dBl = MAKE_SMEM_DESC64(bu + 3*TTILE);
                #pragma unroll
                for (int mh = 0; mh < 2; mh++) {
                    uint64_t dAh = MAKE_SMEM_DESC64(bu + mh*8192);
                    uint64_t dAl = MAKE_SMEM_DESC64(bu + TTILE + mh*8192);
                    uint32_t dacc = tmem + mh*256;
                    #pragma unroll
                    for (int ks = 0; ks < 2; ks++)
                        TCGEN05_MMA_BF16_SS(dacc, dAh + ks*2, dBh + ks*2, idesc,
                                            (c > 0) || (ks > 0));
                    #pragma unroll
                    for (int ks = 0; ks < 2; ks++)
                        TCGEN05_MMA_BF16_SS(dacc, dAh + ks*2, dBl + ks*2, idesc, 1);
                    #pragma unroll
                    for (int ks = 0; ks < 2; ks++)
                        TCGEN05_MMA_BF16_SS(dacc, dAl + ks*2, dBh + ks*2, idesc, 1);
                }
                TCGEN05_COMMIT(mbar_u + buf*8);
            }
        }
    }
    {
        int lb = (NC - 1) & 1;
        if (lb == 0) MBARRIER_WAIT_PARITY(mbar_u,     ph0);
        else         MBARRIER_WAIT_PARITY(mbar_u + 8, ph1);
    }
    TCGEN05_FENCE_AFTER();

    // ---- epilogue: four 128x128 subpasses through SMEM rotation bounce ----
    float* eb = (float*)tb;   // 64KB region reused
    float* Cb = C ? (C + zo*sCo + zi*sCi) : nullptr;
    bf16* Ohb = Oh ? (Oh + zo*sCo + zi*sCi) : nullptr;
    bf16* Olb = Ol ? (Ol + zo*sCo + zi*sCi) : nullptr;
    int nhmax = (N > 128) ? 2 : 1;
    #pragma unroll 1
    for (int mh = 0; mh < 2; mh++) {
        #pragma unroll 1
        for (int nh = 0; nh < nhmax; nh++) {
            if (tid < 128) {
                #pragma unroll 1
                for (int g = 0; g < 4; g++) {
                    uint32_t dr[32];
                    TCGEN05_LD_32X32B_X32(dr, tmem + mh*256 + nh*128 + g*32);
                    TCGEN05_WAIT_LD();
                    #pragma unroll
                    for (int j4 = 0; j4 < 8; j4++) {
                        int grp = g*8 + j4;
                        int rg = (grp + tid) & 31;
                        float4 f4;
                        f4.x = __uint_as_float(dr[j4*4+0]);
                        f4.y = __uint_as_float(dr[j4*4+1]);
                        f4.z = __uint_as_float(dr[j4*4+2]);
                        f4.w = __uint_as_float(dr[j4*4+3]);
                        *(float4*)(eb + (long)tid*128 + rg*4) = f4;
                    }
                }
            }
            __syncthreads();
            #pragma unroll 1
            for (int i = 0; i < 16; i++) {
                int s2 = tid + i*256;
                int row = s2 >> 5, grp = s2 & 31;
                int colb = tn + nh*128 + grp*4;
                if (colb >= N) continue;
                int grow = tm + mh*128 + row;
                float4 f4 = *(float4*)(eb + (long)row*128 + ((grp + row) & 31)*4);
                float v[4] = {f4.x, f4.y, f4.z, f4.w};
                float gate = (epi == 5) ? gates[base + grow] : 1.f;
                #pragma unroll
                for (int jj = 0; jj < 4; jj++) {
                    float t = v[jj]*alpha;
                    int col = colb + jj;
                    if (epi >= 1) t += biasb[col];
                    if (epi == 2) t += extra[(long)(grow & (S-1))*ldc + col];
                    else if (epi == 3) t += extra[(long)grow*ldc + col];
                    else if (epi == 4) t = 0.5f*t*(1.0f + erff(t*0.70710678118654752f));
                    else if (epi == 5) t *= gate;
                    v[jj] = t;
                }
                long cidx = (long)(base + grow)*ldc + colb;
                if (Cb) *(float4*)(Cb + cidx) = make_float4(v[0], v[1], v[2], v[3]);
                if (Ohb) {
                    bf16 h0, l0, h1, l1, h2, l2, h3, l3;
                    split_bf16(v[0], h0, l0); split_bf16(v[1], h1, l1);
                    split_bf16(v[2], h2, l2); split_bf16(v[3], h3, l3);
                    uint2 ph, pl;
                    ph.x = (uint32_t)__bfloat16_as_ushort(h0) | ((uint32_t)__bfloat16_as_ushort(h1) << 16);
                    ph.y = (uint32_t)__bfloat16_as_ushort(h2) | ((uint32_t)__bfloat16_as_ushort(h3) << 16);
                    pl.x = (uint32_t)__bfloat16_as_ushort(l0) | ((uint32_t)__bfloat16_as_ushort(l1) << 16);
                    pl.y = (uint32_t)__bfloat16_as_ushort(l2) | ((uint32_t)__bfloat16_as_ushort(l3) << 16);
                    *(uint2*)(Ohb + cidx) = ph;
                    *(uint2*)(Olb + cidx) = pl;
                }
            }
            __syncthreads();
        }
    }
    TCGEN05_FENCE_BEFORE();
    __syncthreads();
    if (wid == 0) {
        TCGEN05_RELINQ();
        TCGEN05_DEALLOC(tmem, 512);
    }
#else
    // generic fallback (compute_103 PTX stage only; never runs on sm_103a)
    (void)wid; (void)dynsm;
    float* Cb = C ? (C + zo*sCo + zi*sCi) : nullptr;
    bf16* Ohb = Oh ? (Oh + zo*sCo + zi*sCi) : nullptr;
    bf16* Olb = Ol ? (Ol + zo*sCo + zi*sCi) : nullptr;
    for (int rc = tid; rc < GBM*GBN; rc += 256) {
        int r = rc >> 8, c0 = rc & 255;
        int row = tm + r;
        int col = tn + c0;
        if (col >= N) continue;
        long arow = gatherIdx ? (long)gatherIdx[base + row] : (long)(base + row);
        float acc = 0.f;
        for (int k = 0; k < K; k++) {
            float a = __bfloat162float(Abh[arow*lda + k]) + __bfloat162float(Abl[arow*lda + k]);
            float b = __bfloat162float(Bbh[(long)col*ldb + k]) + __bfloat162float(Bbl[(long)col*ldb + k]);
            acc = fmaf(a, b, acc);
        }
        float t = acc*alpha;
        if (epi >= 1) t += biasb[col];
        if (epi == 2) t += extra[(long)(row & (S-1))*ldc + col];
        else if (epi == 3) t += extra[(long)row*ldc + col];
        else if (epi == 4) t = 0.5f*t*(1.0f + erff(t*0.70710678118654752f));
        else if (epi == 5) t *= gates[base + row];
        long cidx = (long)(base + row)*ldc + col;
        if (Cb) Cb[cidx] = t;
        if (Ohb) { bf16 h, l; split_bf16(t, h, l); Ohb[cidx] = h; Olb[cidx] = l; }
    }
#endif
}

// ---------------- small FFMA GEMM for the cls head (M=32) ------------------
#define OBM 64
#define OBN 64
#define OBK 16
__global__ void gemm_k(const float* __restrict__ A, const float* __restrict__ B,
                       float* __restrict__ C, int M, int N, int K,
                       int lda, int ldb, int ldc,
                       const float* __restrict__ bias)
{
    __shared__ float As[OBK][OBM];
    __shared__ float Bs[OBK][OBN+4];
    int tm = blockIdx.x*OBM;
    int tn = blockIdx.y*OBN;
    int tid = threadIdx.x;
    int tx = tid & 15, ty = tid >> 4;
    float acc[4][4] = {};
    for (int k0 = 0; k0 < K; k0 += OBK) {
        #pragma unroll
        for (int t = 0; t < 4; t++) {
            int id = tid + t*256;
            int r = id >> 4, c = id & 15;
            int gr = tm + r;
            float v = 0.f;
            if (gr < M && (k0 + c) < K) v = A[(long)gr*lda + k0 + c];
            As[c][r] = v;
        }
        #pragma unroll
        for (int t = 0; t < 4; t++) {
            int id = tid + t*256;
            int r = id >> 6, c = id & 63;
            float v = 0.f;
            if ((k0 + r) < K && (tn + c) < N) v = B[(long)(k0 + r)*ldb + tn + c];
            Bs[r][c] = v;
        }
        __syncthreads();
        #pragma unroll
        for (int kk = 0; kk < OBK; kk++) {
            float av[4], bv[4];
            #pragma unroll
            for (int i = 0; i < 4; i++) av[i] = As[kk][ty*4 + i];
            #pragma unroll
            for (int j = 0; j < 4; j++) bv[j] = Bs[kk][tx*4 + j];
            #pragma unroll
            for (int i = 0; i < 4; i++)
                #pragma unroll
                for (int j = 0; j < 4; j++)
                    acc[i][j] = fmaf(av[i], bv[j], acc[i][j]);
        }
        __syncthreads();
    }
    #pragma unroll
    for (int i = 0; i < 4; i++) {
        int row = tm + ty*4 + i;
        if (row >= M) continue;
        #pragma unroll
        for (int j = 0; j < 4; j++) {
            int col = tn + tx*4 + j;
            if (col >= N) continue;
            C[(long)row*ldc + col] = acc[i][j] + bias[col];
        }
    }
}

// ---------------- layernorm: fp32 out + split bf16 out ---------------------
__global__ void ln_k(const float* __restrict__ x, const float* __restrict__ g,
                     const float* __restrict__ b, float* __restrict__ y,
                     bf16* __restrict__ yh, bf16* __restrict__ yl)
{
    int row  = (blockIdx.x*blockDim.x + threadIdx.x) >> 5;
    int lane = threadIdx.x & 31;
    if (row >= T) return;
    const float* xr = x + (long)row*D;
    float v[16]; float s = 0.f;
    #pragma unroll
    for (int i = 0; i < 16; i++) { v[i] = xr[lane + 32*i]; s += v[i]; }
    #pragma unroll
    for (int o = 16; o > 0; o >>= 1) s += __shfl_xor_sync(~0u, s, o);
    float mean = s*(1.f/D);
    float vs = 0.f;
    #pragma unroll
    for (int i = 0; i < 16; i++) { float d = v[i]-mean; vs += d*d; }
    #pragma unroll
    for (int o = 16; o > 0; o >>= 1) vs += __shfl_xor_sync(~0u, vs, o);
    float rstd = rsqrtf(vs*(1.f/D) + 1e-5f);
    float* yr = y + (long)row*D;
    bf16* yhr = yh + (long)row*D;
    bf16* ylr = yl + (long)row*D;
    #pragma unroll
    for (int i = 0; i < 16; i++) {
        int c = lane + 32*i;
        float o = (v[i]-mean)*rstd*g[c] + b[c];
        yr[c] = o;
        bf16 h, l; split_bf16(o, h, l);
        yhr[c] = h; ylr[c] = l;
    }
}

// ---------------- softmax (256): fp32 in-place + split out -----------------
__global__ void softmax_k(float* __restrict__ a, int rows,
                          bf16* __restrict__ oh, bf16* __restrict__ ol)
{
    int row  = (blockIdx.x*blockDim.x + threadIdx.x) >> 5;
    int lane = threadIdx.x & 31;
    if (row >= rows) return;
    float* r = a + (long)row*S;
    bf16* rh = oh + (long)row*S;
    bf16* rl = ol + (long)row*S;
    float v[8]; float m = -1e30f;
    #pragma unroll
    for (int i = 0; i < 8; i++) { v[i] = r[lane + 32*i]; m = fmaxf(m, v[i]); }
    #pragma unroll
    for (int o = 16; o > 0; o >>= 1) m = fmaxf(m, __shfl_xor_sync(~0u, m, o));
    float s = 0.f;
    #pragma unroll
    for (int i = 0; i < 8; i++) { v[i] = expf(v[i]-m); s += v[i]; }
    #pragma unroll
    for (int o = 16; o > 0; o >>= 1) s += __shfl_xor_sync(~0u, s, o);
    float inv = 1.f/s;
    #pragma unroll
    for (int i = 0; i < 8; i++) {
        int c = lane + 32*i;
        float p = v[i]*inv;
        r[c] = p;
        bf16 h, l; split_bf16(p, h, l);
        rh[c] = h; rl[c] = l;
    }
}

// ---------------- head-mean + re-softmax -> attn_w -------------------------
__global__ void attnw_k(const float* __restrict__ attn, float* __restrict__ out)
{
    int row  = (blockIdx.x*blockDim.x + threadIdx.x) >> 5;
    int lane = threadIdx.x & 31;
    if (row >= T) return;
    int b = row >> 8, i = row & 255;
    const float* base = attn + ((long)b*NH*S + i)*S;
    float v[8];
    #pragma unroll
    for (int t = 0; t < 8; t++) {
        int j = lane + 32*t; float s = 0.f;
        #pragma unroll
        for (int h = 0; h < NH; h++) s += base[(long)h*S*S + j];
        v[t] = s*0.125f;
    }
    float m = -1e30f;
    #pragma unroll
    for (int t = 0; t < 8; t++) m = fmaxf(m, v[t]);
    #pragma unroll
    for (int o = 16; o > 0; o >>= 1) m = fmaxf(m, __shfl_xor_sync(~0u, m, o));
    float s = 0.f;
    #pragma unroll
    for (int t = 0; t < 8; t++) { v[t] = expf(v[t]-m); s += v[t]; }
    #pragma unroll
    for (int o = 16; o > 0; o >>= 1) s += __shfl_xor_sync(~0u, s, o);
    float inv = 1.f/s;
    float* orow = out + (long)row*S;
    #pragma unroll
    for (int t = 0; t < 8; t++) orow[lane + 32*t] = v[t]*inv;
}

// ---------------- MoE routing ----------------------------------------------
__global__ void route_k(const float* __restrict__ xln, const float* __restrict__ rw,
                        const float* __restrict__ rb, float* __restrict__ probs,
                        int* __restrict__ topi, float* __restrict__ topv)
{
    int tok  = (blockIdx.x*blockDim.x + threadIdx.x) >> 5;
    int lane = threadIdx.x & 31;
    if (tok >= T) return;
    const float* xr = xln + (long)tok*D;
    float acc[E] = {};
    for (int d = lane; d < D; d += 32) {
        float xv = xr[d];
        #pragma unroll
        for (int e = 0; e < E; e++) acc[e] = fmaf(xv, rw[d*E + e], acc[e]);
    }
    #pragma unroll
    for (int e = 0; e < E; e++)
        #pragma unroll
        for (int o = 16; o > 0; o >>= 1) acc[e] += __shfl_xor_sync(~0u, acc[e], o);
    if (lane == 0) {
        float mx = -1e30f;
        #pragma unroll
        for (int e = 0; e < E; e++) { acc[e] += rb[e]; mx = fmaxf(mx, acc[e]); }
        float s = 0.f, p[E];
        #pragma unroll
        for (int e = 0; e < E; e++) { p[e] = expf(acc[e]-mx); s += p[e]; }
        float inv = 1.f/s;
        int i0 = 0; float v0 = -1.f;
        #pragma unroll
        for (int e = 0; e < E; e++) { p[e] *= inv; probs[(long)tok*E + e] = p[e];
                                      if (p[e] > v0) { v0 = p[e]; i0 = e; } }
        int i1 = 0; float v1 = -1.f;
        #pragma unroll
        for (int e = 0; e < E; e++) { if (e != i0 && p[e] > v1) { v1 = p[e]; i1 = e; } }
        topi[tok*2] = i0;  topv[tok*2] = v0;
        topi[tok*2+1] = i1; topv[tok*2+1] = v1;
    }
}

// ---------------- bucket build (pad per-expert to 256) ---------------------
__global__ void bucket_k(const int* __restrict__ topi, const float* __restrict__ topv,
                         int* __restrict__ btok, float* __restrict__ bgate,
                         int* __restrict__ slot, int* __restrict__ eoff,
                         int* __restrict__ ecnt, int* __restrict__ ecnt_raw)
{
    __shared__ int cnt[E], off[E], cur[E];
    int tid = threadIdx.x;
    if (tid < E) cnt[tid] = 0;
    __syncthreads();
    for (int t = tid; t < T; t += 256) {
        atomicAdd(&cnt[topi[t*2]], 1);
        atomicAdd(&cnt[topi[t*2+1]], 1);
    }
    __syncthreads();
    if (tid == 0) {
        int o = 0;
        for (int e = 0; e < E; e++) { off[e] = o; o += (cnt[e] + GBM - 1) & ~(GBM - 1); }
    }
    __syncthreads();
    if (tid < E) {
        cur[tid] = off[tid];
        eoff[tid] = off[tid];
        ecnt[tid] = cnt[tid];
        ecnt_raw[tid] = cnt[tid];
    }
    __syncthreads();
    for (int t = tid; t < T; t += 256) {
        #pragma unroll
        for (int k = 0; k < 2; k++) {
            int e = topi[t*2 + k];
            int pos = atomicAdd(&cur[e], 1);
            btok[pos] = t;
            bgate[pos] = topv[t*2 + k];
            slot[t*2 + k] = pos;
        }
    }
    __syncthreads();
    for (int e = 0; e < E; e++) {
        int start = off[e] + cnt[e];
        int end   = off[e] + ((cnt[e] + GBM - 1) & ~(GBM - 1));
        for (int p = start + tid; p < end; p += 256) { btok[p] = 0; bgate[p] = 0.f; }
    }
}

// ---------------- combine 2 slot contributions -----------------------------
__global__ void combine_k(const int* __restrict__ slot, const float* __restrict__ contrib,
                          float* __restrict__ out)
{
    long idx = (long)blockIdx.x*blockDim.x + threadIdx.x;
    if (idx >= (long)T*D) return;
    int t = (int)(idx >> 9), d = (int)(idx & 511);
    int s0 = slot[t*2], s1 = slot[t*2+1];
    out[idx] = contrib[(long)s0*D + d] + contrib[(long)s1*D + d];
}

// ---------------- aux loss -------------------------------------------------
__global__ void loss_k(const float* __restrict__ probs, const int* __restrict__ ecnt_raw,
                       float* __restrict__ out, int accum)
{
    __shared__ float red[256*E];
    int tid = threadIdx.x;
    float acc[E] = {};
    for (int t = tid; t < T; t += 256)
        #pragma unroll
        for (int e = 0; e < E; e++) acc[e] += probs[(long)t*E + e];
    #pragma unroll
    for (int e = 0; e < E; e++) red[tid*E + e] = acc[e];
    __syncthreads();
    for (int s = 128; s > 0; s >>= 1) {
        if (tid < s)
            #pragma unroll
            for (int e = 0; e < E; e++) red[tid*E + e] += red[(tid + s)*E + e];
        __syncthreads();
    }
    if (tid == 0) {
        float l = 0.f;
        for (int e = 0; e < E; e++) {
            float imp  = red[e]*(1.f/T);
            float frac = (float)ecnt_raw[e]*(1.f/T);
            l += frac*imp;
        }
        l *= (float)E;
        if (accum) out[0] += l; else out[0] = l;
    }
}

// ---------------- fv mean over S -------------------------------------------
__global__ void fv_k(const float* __restrict__ o2, float* __restrict__ fv)
{
    int b = blockIdx.x, d = threadIdx.x;
    float s = 0.f;
    for (int i = 0; i < S; i++) s += o2[((long)b*S + i)*D + d];
    fv[b*D + d] = s*(1.f/S);
}

__global__ void writeloss_k(const float* __restrict__ loss, float* __restrict__ out)
{
    out[0] = loss[0];
}

// ---------------- host -----------------------------------------------------
#define SYM(p, s) cudaGetSymbolAddress((void**)&p, s)
#define IDESC(N) (IDESC_BASE | (((uint32_t)(N)/8u) << 17))

extern "C" void kernel_launch(void* const* d_in, const int* in_sizes, int n_in,
                              void* d_out, int out_size)
{
    const float* x    = (const float*)d_in[0];
    const float* pe_w = (const float*)d_in[1];
    const float* pe_b = (const float*)d_in[2];
    const float* pos  = (const float*)d_in[3];
    const float* ln1g = (const float*)d_in[4];
    const float* ln1b = (const float*)d_in[5];
    const float* ln2g = (const float*)d_in[6];
    const float* ln2b = (const float*)d_in[7];
    const float* ln3g = (const float*)d_in[8];
    const float* ln3b = (const float*)d_in[9];
    const float* wq = (const float*)d_in[10]; const float* bq = (const float*)d_in[11];
    const float* wk = (const float*)d_in[12]; const float* bk = (const float*)d_in[13];
    const float* wv = (const float*)d_in[14]; const float* bv = (const float*)d_in[15];
    const float* wo = (const float*)d_in[16]; const float* bo = (const float*)d_in[17];
    const float* m1rw = (const float*)d_in[18]; const float* m1rb = (const float*)d_in[19];
    const float* m1w1 = (const float*)d_in[20]; const float* m1b1 = (const float*)d_in[21];
    const float* m1w2 = (const float*)d_in[22]; const float* m1b2 = (const float*)d_in[23];
    const float* m2rw = (const float*)d_in[24]; const float* m2rb = (const float*)d_in[25];
    const float* m2w1 = (const float*)d_in[26]; const float* m2b1 = (const float*)d_in[27];
    const float* m2w2 = (const float*)d_in[28]; const float* m2b2 = (const float*)d_in[29];
    const float* clsw = (const float*)d_in[30]; const float* clsb = (const float*)d_in[31];
    float* out = (float*)d_out;

    cudaFuncSetAttribute(tgemm_k, cudaFuncAttributeMaxDynamicSharedMemorySize, DYNSM);

    float *p_e, *p_ln, *p_v, *p_attn, *p_x2, *p_contrib, *p_o1, *p_o2;
    float *p_probs, *p_topv, *p_bgate, *p_loss;
    int *p_topi, *p_btok, *p_slot, *p_eoff, *p_ecnt, *p_ecnt_raw;
    bf16 *patH,*patL,*lnH,*lnL,*qH,*qL,*kH,*kL,*vTH,*vTL,*attnH,*attnL,*avH,*avL,*hbH,*hbL;
    bf16 *petH,*petL,*wqtH,*wqtL,*wktH,*wktL,*wvtH,*wvtL,*wotH,*wotL;
    bf16 *w1aH,*w1aL,*w2aH,*w2aL,*w1bH,*w1bL,*w2bH,*w2bL;
    SYM(p_e, g_e); SYM(p_ln, g_ln); SYM(p_v, g_v); SYM(p_attn, g_attn);
    SYM(p_x2, g_x2); SYM(p_contrib, g_contrib); SYM(p_o1, g_o1); SYM(p_o2, g_o2);
    SYM(p_probs, g_probs); SYM(p_topv, g_topv); SYM(p_bgate, g_bgate); SYM(p_loss, g_loss);
    SYM(p_topi, g_topi); SYM(p_btok, g_btok); SYM(p_slot, g_slot);
    SYM(p_eoff, g_eoff); SYM(p_ecnt, g_ecnt); SYM(p_ecnt_raw, g_ecnt_raw);
    SYM(patH, g_patH); SYM(patL, g_patL); SYM(lnH, g_lnH); SYM(lnL, g_lnL);
    SYM(qH, g_qH); SYM(qL, g_qL); SYM(kH, g_kH); SYM(kL, g_kL);
    SYM(vTH, g_vTH); SYM(vTL, g_vTL); SYM(attnH, g_attnH); SYM(attnL, g_attnL);
    SYM(avH, g_avH); SYM(avL, g_avL); SYM(hbH, g_hbufH); SYM(hbL, g_hbufL);
    SYM(petH, g_petH); SYM(petL, g_petL); SYM(wqtH, g_wqtH); SYM(wqtL, g_wqtL);
    SYM(wktH, g_wktH); SYM(wktL, g_wktL); SYM(wvtH, g_wvtH); SYM(wvtL, g_wvtL);
    SYM(wotH, g_wotH); SYM(wotL, g_wotL);
    SYM(w1aH, g_w1t1H); SYM(w1aL, g_w1t1L); SYM(w2aH, g_w2t1H); SYM(w2aL, g_w2t1L);
    SYM(w1bH, g_w1t2H); SYM(w1bL, g_w1t2L); SYM(w2bH, g_w2t2H); SYM(w2bL, g_w2t2L);

    dim3 tt(32, 8);
    long Z6 = 0;
    // patchify + pe_w transpose + embed GEMM
    { long tot = (long)T*PDK;
      patchify_k<<<(int)((tot + 255)/256), 256>>>(x, patH, patL); }
    wtrans_k<<<dim3(16, 20, 1), tt>>>(pe_w, petH, petL, PD, D, PDK);
    tgemm_k<<<dim3(T/GBM, D/GBN, 1), 256, DYNSM>>>(patH, patL, petH, petL,
        p_e, nullptr, nullptr, T, D, PDK, PDK, PDK, D, IDESC(256),
        Z6,Z6,Z6,Z6,Z6,Z6,1, 1.f, pe_b, 0, pos, nullptr, nullptr, nullptr, nullptr, 2);
    ln_k<<<T*32/256, 256>>>(p_e, ln1g, ln1b, p_ln, lnH, lnL);
    // qkv
    wtrans_k<<<dim3(16, 16, 1), tt>>>(wq, wqtH, wqtL, D, D, D);
    tgemm_k<<<dim3(T/GBM, D/GBN, 1), 256, DYNSM>>>(lnH, lnL, wqtH, wqtL,
        nullptr, qH, qL, T, D, D, D, D, D, IDESC(256),
        Z6,Z6,Z6,Z6,Z6,Z6,1, 1.f, bq, 0, nullptr, nullptr, nullptr, nullptr, nullptr, 1);
    wtrans_k<<<dim3(16, 16, 1), tt>>>(wk, wktH, wktL, D, D, D);
    tgemm_k<<<dim3(T/GBM, D/GBN, 1), 256, DYNSM>>>(lnH, lnL, wktH, wktL,
        nullptr, kH, kL, T, D, D, D, D, D, IDESC(256),
        Z6,Z6,Z6,Z6,Z6,Z6,1, 1.f, bk, 0, nullptr, nullptr, nullptr, nullptr, nullptr, 1);
    wtrans_k<<<dim3(16, 16, 1), tt>>>(wv, wvtH, wvtL, D, D, D);
    tgemm_k<<<dim3(T/GBM, D/GBN, 1), 256, DYNSM>>>(lnH, lnL, wvtH, wvtL,
        p_v, nullptr, nullptr, T, D, D, D, D, D, IDESC(256),
        Z6,Z6,Z6,Z6,Z6,Z6,1, 1.f, bv, 0, nullptr, nullptr, nullptr, nullptr, nullptr, 1);
    { long tot = (long)Bt*NH*HD*S;
      ktrans_k<<<(int)((tot + 255)/256), 256>>>(p_v, vTH, vTL); }
    // scores = q @ k^T / 8  (one 256x256 tile per (b,h))
    tgemm_k<<<dim3(1, 1, Bt*NH), 256, DYNSM>>>(qH, qL, kH, kL,
        p_attn, nullptr, nullptr, S, S, HD, D, D, S, IDESC(256),
        (long)S*D, (long)HD, (long)S*D, (long)HD, (long)NH*S*S, (long)S*S, NH,
        0.125f, nullptr, 0, nullptr, nullptr, nullptr, nullptr, nullptr, 0);
    softmax_k<<<Bt*NH*S*32/256, 256>>>(p_attn, Bt*NH*S, attnH, attnL);
    attnw_k<<<T*32/256, 256>>>(p_attn, out + 32769);
    // av = attn @ v  (N=64)
    tgemm_k<<<dim3(1, 1, Bt*NH), 256, DYNSM>>>(attnH, attnL, vTH, vTL,
        nullptr, avH, avL, S, HD, S, S, S, D, IDESC(64),
        (long)NH*S*S, (long)S*S, (long)NH*HD*S, (long)HD*S, (long)S*D, (long)HD, NH,
        1.f, nullptr, 0, nullptr, nullptr, nullptr, nullptr, nullptr, 0);
    // out proj + residual
    wtrans_k<<<dim3(16, 16, 1), tt>>>(wo, wotH, wotL, D, D, D);
    tgemm_k<<<dim3(T/GBM, D/GBN, 1), 256, DYNSM>>>(avH, avL, wotH, wotL,
        p_x2, nullptr, nullptr, T, D, D, D, D, D, IDESC(256),
        Z6,Z6,Z6,Z6,Z6,Z6,1, 1.f, bo, 0, p_e, nullptr, nullptr, nullptr, nullptr, 3);

    // ----- MoE layer 1 -----
    ln_k<<<T*32/256, 256>>>(p_x2, ln2g, ln2b, p_ln, lnH, lnL);
    route_k<<<T*32/256, 256>>>(p_ln, m1rw, m1rb, p_probs, p_topi, p_topv);
    bucket_k<<<1, 256>>>(p_topi, p_topv, p_btok, p_bgate, p_slot, p_eoff, p_ecnt, p_ecnt_raw);
    wtrans_k<<<dim3(64, 16, E), tt>>>(m1w1, w1aH, w1aL, D, HID, D);
    tgemm_k<<<dim3(64, HID/GBN, E), 256, DYNSM>>>(lnH, lnL, w1aH, w1aL,
        nullptr, hbH, hbL, 0, HID, D, D, D, HID, IDESC(256),
        Z6,Z6,(long)HID*D,Z6,Z6,Z6,1, 1.f, m1b1, HID, nullptr, p_btok, nullptr,
        p_eoff, p_ecnt, 4);
    wtrans_k<<<dim3(16, 64, E), tt>>>(m1w2, w2aH, w2aL, HID, D, HID);
    tgemm_k<<<dim3(64, D/GBN, E), 256, DYNSM>>>(hbH, hbL, w2aH, w2aL,
        p_contrib, nullptr, nullptr, 0, D, HID, HID, HID, D, IDESC(256),
        Z6,Z6,(long)D*HID,Z6,Z6,Z6,1, 1.f, m1b2, D, nullptr, nullptr, p_bgate,
        p_eoff, p_ecnt, 5);
    combine_k<<<T*D/256, 256>>>(p_slot, p_contrib, p_o1);
    loss_k<<<1, 256>>>(p_probs, p_ecnt_raw, p_loss, 0);

    // ----- MoE layer 2 -----
    ln_k<<<T*32/256, 256>>>(p_o1, ln3g, ln3b, p_ln, lnH, lnL);
    route_k<<<T*32/256, 256>>>(p_ln, m2rw, m2rb, p_probs, p_topi, p_topv);
    bucket_k<<<1, 256>>>(p_topi, p_topv, p_btok, p_bgate, p_slot, p_eoff, p_ecnt, p_ecnt_raw);
    wtrans_k<<<dim3(64, 16, E), tt>>>(m2w1, w1bH, w1bL, D, HID, D);
    tgemm_k<<<dim3(64, HID/GBN, E), 256, DYNSM>>>(lnH, lnL, w1bH, w1bL,
        nullptr, hbH, hbL, 0, HID, D, D, D, HID, IDESC(256),
        Z6,Z6,(long)HID*D,Z6,Z6,Z6,1, 1.f, m2b1, HID, nullptr, p_btok, nullptr,
        p_eoff, p_ecnt, 4);
    wtrans_k<<<dim3(16, 64, E), tt>>>(m2w2, w2bH, w2bL, HID, D, HID);
    tgemm_k<<<dim3(64, D/GBN, E), 256, DYNSM>>>(hbH, hbL, w2bH, w2bL,
        p_contrib, nullptr, nullptr, 0, D, HID, HID, HID, D, IDESC(256),
        Z6,Z6,(long)D*HID,Z6,Z6,Z6,1, 1.f, m2b2, D, nullptr, nullptr, p_bgate,
        p_eoff, p_ecnt, 5);
    combine_k<<<T*D/256, 256>>>(p_slot, p_contrib, p_o2);
    loss_k<<<1, 256>>>(p_probs, p_ecnt_raw, p_loss, 1);

    // fv, logits, loss
    fv_k<<<Bt, D>>>(p_o2, out + 16384);
    gemm_k<<<dim3(1, D/OBN, 1), 256>>>(out + 16384, clsw, out, Bt, D, D, D, D, D, clsb);
    writeloss_k<<<1, 1>>>(p_loss, out + 32768);
}